// round 1
// baseline (speedup 1.0000x reference)
#include <cuda_runtime.h>
#include <math.h>

// ---------------- problem constants ----------------
#define D_MODEL 1024
#define NHEAD   16
#define HEAD_DIM 64
#define FF      4096
#define ALPHA   1.4142135f
#define EPS     1e-5f
#define BATCH   2
#define SEQ     2048
#define MTOT    (BATCH*SEQ)        // 4096 rows

// ---------------- scratch (device globals; no allocation allowed) ------------
__device__ float g_qkv[(size_t)MTOT * 3 * D_MODEL];        // 4096 x 3072
__device__ float g_q  [(size_t)BATCH * NHEAD * SEQ * HEAD_DIM];
__device__ float g_k  [(size_t)BATCH * NHEAD * SEQ * HEAD_DIM];
__device__ float g_v  [(size_t)BATCH * NHEAD * SEQ * HEAD_DIM];
__device__ float g_o  [(size_t)MTOT * D_MODEL];            // attention out, [B,T,d]
__device__ float g_a  [(size_t)MTOT * D_MODEL];            // Wout GEMM out
__device__ float g_x2 [(size_t)MTOT * D_MODEL];            // post-norm1
__device__ float g_yg [(size_t)MTOT * 2 * FF];             // 4096 x 8192
__device__ float g_hb [(size_t)MTOT * FF];                 // swiglu out
__device__ float g_y2 [(size_t)MTOT * D_MODEL];            // W2 GEMM out

// ---------------- SGEMM: C[M,N] = A[M,K] * B[N,K]^T  (both row-major) --------
#define BM 128
#define BN 128
#define BKK 16

__global__ void __launch_bounds__(256, 1)
sgemm_nt(const float* __restrict__ A, const float* __restrict__ Bw,
         float* __restrict__ C, int M, int N, int K)
{
    __shared__ float As[BKK][132];
    __shared__ float Bs[BKK][132];

    const int tid = threadIdx.x;
    const int tx = tid & 15;         // 0..15 -> N microtile
    const int ty = tid >> 4;         // 0..15 -> M microtile
    const int bm = blockIdx.y * BM;
    const int bn = blockIdx.x * BN;

    // loading map: thread loads 2 float4 for A and 2 for B
    const int r0 = tid >> 2;         // 0..63
    const int c0 = (tid & 3) * 4;    // 0,4,8,12

    float acc[8][8];
#pragma unroll
    for (int i = 0; i < 8; i++)
#pragma unroll
        for (int j = 0; j < 8; j++) acc[i][j] = 0.f;

    float4 pa0, pa1, pb0, pb1;

    const int NK = K / BKK;

    // prologue load (tile 0)
    {
        const float* Ab = A + (size_t)(bm + r0) * K + c0;
        pa0 = *(const float4*)Ab;
        pa1 = *(const float4*)(Ab + (size_t)64 * K);
        const float* Bb = Bw + (size_t)(bn + r0) * K + c0;
        pb0 = *(const float4*)Bb;
        pb1 = *(const float4*)(Bb + (size_t)64 * K);
    }

    auto store_tiles = [&]() {
        As[c0+0][r0] = pa0.x; As[c0+1][r0] = pa0.y; As[c0+2][r0] = pa0.z; As[c0+3][r0] = pa0.w;
        As[c0+0][r0+64] = pa1.x; As[c0+1][r0+64] = pa1.y; As[c0+2][r0+64] = pa1.z; As[c0+3][r0+64] = pa1.w;
        Bs[c0+0][r0] = pb0.x; Bs[c0+1][r0] = pb0.y; Bs[c0+2][r0] = pb0.z; Bs[c0+3][r0] = pb0.w;
        Bs[c0+0][r0+64] = pb1.x; Bs[c0+1][r0+64] = pb1.y; Bs[c0+2][r0+64] = pb1.z; Bs[c0+3][r0+64] = pb1.w;
    };
    store_tiles();
    __syncthreads();

    for (int kt = 0; kt < NK; kt++) {
        if (kt + 1 < NK) {
            const float* Ab = A + (size_t)(bm + r0) * K + (size_t)(kt + 1) * BKK + c0;
            pa0 = *(const float4*)Ab;
            pa1 = *(const float4*)(Ab + (size_t)64 * K);
            const float* Bb = Bw + (size_t)(bn + r0) * K + (size_t)(kt + 1) * BKK + c0;
            pb0 = *(const float4*)Bb;
            pb1 = *(const float4*)(Bb + (size_t)64 * K);
        }
#pragma unroll
        for (int k = 0; k < BKK; k++) {
            float4 a0 = *(const float4*)&As[k][ty * 4];
            float4 a1 = *(const float4*)&As[k][ty * 4 + 64];
            float4 b0 = *(const float4*)&Bs[k][tx * 4];
            float4 b1 = *(const float4*)&Bs[k][tx * 4 + 64];
            float av[8] = {a0.x, a0.y, a0.z, a0.w, a1.x, a1.y, a1.z, a1.w};
            float bv[8] = {b0.x, b0.y, b0.z, b0.w, b1.x, b1.y, b1.z, b1.w};
#pragma unroll
            for (int i = 0; i < 8; i++)
#pragma unroll
                for (int j = 0; j < 8; j++)
                    acc[i][j] += av[i] * bv[j];
        }
        __syncthreads();
        if (kt + 1 < NK) {
            store_tiles();
            __syncthreads();
        }
    }

    // epilogue
#pragma unroll
    for (int i = 0; i < 8; i++) {
        int mrow = bm + ((i < 4) ? (ty * 4 + i) : (64 + ty * 4 + (i - 4)));
        float* Crow = C + (size_t)mrow * N + bn;
        *(float4*)&Crow[tx * 4]      = make_float4(acc[i][0], acc[i][1], acc[i][2], acc[i][3]);
        *(float4*)&Crow[tx * 4 + 64] = make_float4(acc[i][4], acc[i][5], acc[i][6], acc[i][7]);
    }
}

// ---------------- RoPE + split into [B,H,T,Dh] -------------------------------
__global__ void __launch_bounds__(256)
rope_split(const float* __restrict__ qkv,
           float* __restrict__ Q, float* __restrict__ K, float* __restrict__ V)
{
    int i = blockIdx.x * blockDim.x + threadIdx.x;      // over B*T*H*32
    int d = i & 31;
    int h = (i >> 5) & (NHEAD - 1);
    int t = (i >> 9) & (SEQ - 1);
    int b = i >> (9 + 11);
    if (b >= BATCH) return;

    const float* base = qkv + ((size_t)(b * SEQ + t) * 3) * D_MODEL + h * HEAD_DIM;
    float q1 = base[d],               q2 = base[d + 32];
    float k1 = base[D_MODEL + d],     k2 = base[D_MODEL + d + 32];
    float v1 = base[2 * D_MODEL + d], v2 = base[2 * D_MODEL + d + 32];

    float inv = powf(10000.0f, -(float)d / 32.0f);
    float ang = (float)t * inv;
    float c = cosf(ang), s = sinf(ang);

    size_t o = (((size_t)(b * NHEAD + h) * SEQ) + t) * HEAD_DIM;
    Q[o + d]      = q1 * c - q2 * s;
    Q[o + d + 32] = q2 * c + q1 * s;
    K[o + d]      = k1 * c - k2 * s;
    K[o + d + 32] = k2 * c + k1 * s;
    V[o + d]      = v1;
    V[o + d + 32] = v2;
}

// ---------------- banded attention -------------------------------------------
// window: key in [q-127, q+128]. Block = (b,h, 64-query tile). Key span <= 319.
#define QTILE 64
#define KSPAN 320
#define KPAD  68

__global__ void __launch_bounds__(256)
attn_kernel(const float* __restrict__ Q, const float* __restrict__ K,
            const float* __restrict__ V, float* __restrict__ O)
{
    extern __shared__ float sm[];
    float* Ks = sm;                        // KSPAN*KPAD
    float* Vs = Ks + KSPAN * KPAD;         // KSPAN*KPAD
    float* Qs = Vs + KSPAN * KPAD;         // QTILE*KPAD
    float* Pr = Qs + QTILE * KPAD;         // 8*KSPAN (per-warp prob rows)

    const int bh = blockIdx.y;             // b*NHEAD + h
    const int q0 = blockIdx.x * QTILE;
    const int klo = max(0, q0 - 127);
    const int khi = min(SEQ - 1, q0 + QTILE - 1 + 128);
    const int nk = khi - klo + 1;

    const int tid = threadIdx.x;
    const float* Kb = K + (size_t)bh * SEQ * HEAD_DIM;
    const float* Vb = V + (size_t)bh * SEQ * HEAD_DIM;
    const float* Qb = Q + (size_t)bh * SEQ * HEAD_DIM;

    for (int i = tid; i < nk * HEAD_DIM; i += 256) {
        int r = i >> 6, d = i & 63;
        Ks[r * KPAD + d] = Kb[(size_t)(klo + r) * HEAD_DIM + d];
        Vs[r * KPAD + d] = Vb[(size_t)(klo + r) * HEAD_DIM + d];
    }
    for (int i = tid; i < QTILE * HEAD_DIM; i += 256) {
        int r = i >> 6, d = i & 63;
        Qs[r * KPAD + d] = Qb[(size_t)(q0 + r) * HEAD_DIM + d];
    }
    __syncthreads();

    const int w = tid >> 5, lane = tid & 31;
    float* P = Pr + w * KSPAN;
    const int b = bh / NHEAD, h = bh % NHEAD;

    for (int j = 0; j < 8; j++) {
        const int ql = w * 8 + j;
        const int q = q0 + ql;
        const int lo = max(0, q - 127) - klo;
        const int hi = min(SEQ - 1, q + 128) - klo;

        // q row -> registers (vectorized)
        float4 qv[16];
        const float4* qr4 = (const float4*)&Qs[ql * KPAD];
#pragma unroll
        for (int d = 0; d < 16; d++) qv[d] = qr4[d];

        // scores + running max (each lane strides the key range)
        float m = -INFINITY;
        for (int kk = lo + lane; kk <= hi; kk += 32) {
            const float4* kr4 = (const float4*)&Ks[kk * KPAD];
            float s = 0.f;
#pragma unroll
            for (int d = 0; d < 16; d++) {
                float4 kvv = kr4[d];
                s += qv[d].x * kvv.x + qv[d].y * kvv.y + qv[d].z * kvv.z + qv[d].w * kvv.w;
            }
            s *= 0.125f;                 // 1/sqrt(64)
            P[kk] = s;
            m = fmaxf(m, s);
        }
#pragma unroll
        for (int o = 16; o; o >>= 1) m = fmaxf(m, __shfl_xor_sync(0xffffffffu, m, o));

        float sum = 0.f;
        for (int kk = lo + lane; kk <= hi; kk += 32) {
            float e = expf(P[kk] - m);
            P[kk] = e;
            sum += e;
        }
#pragma unroll
        for (int o = 16; o; o >>= 1) sum += __shfl_xor_sync(0xffffffffu, sum, o);
        const float invs = 1.f / sum;
        __syncwarp();

        // output: lane owns dims (2*lane, 2*lane+1)
        float2 acc = make_float2(0.f, 0.f);
        for (int kk = lo; kk <= hi; kk++) {
            float p = P[kk];
            float2 vv = *(const float2*)&Vs[kk * KPAD + 2 * lane];
            acc.x += p * vv.x;
            acc.y += p * vv.y;
        }
        float* orow = O + ((size_t)(b * SEQ + q)) * D_MODEL + h * HEAD_DIM;
        ((float2*)orow)[lane] = make_float2(acc.x * invs, acc.y * invs);
        __syncwarp();
    }
}

// ---------------- residual + (opt bias) + RMSNorm ----------------------------
__global__ void __launch_bounds__(256)
resid_rmsnorm(const float* __restrict__ A, const float* __restrict__ bias,
              const float* __restrict__ R, const float* __restrict__ g,
              float* __restrict__ out)
{
    const int row = blockIdx.x;
    const float* a = A + (size_t)row * D_MODEL;
    const float* r = R + (size_t)row * D_MODEL;

    float v[4];
    float ss = 0.f;
#pragma unroll
    for (int i = 0; i < 4; i++) {
        int c = threadIdx.x + i * 256;
        float x = a[c] + ALPHA * r[c];
        if (bias) x += bias[c];
        v[i] = x;
        ss += x * x;
    }
#pragma unroll
    for (int o = 16; o; o >>= 1) ss += __shfl_xor_sync(0xffffffffu, ss, o);

    __shared__ float ws[8];
    if ((threadIdx.x & 31) == 0) ws[threadIdx.x >> 5] = ss;
    __syncthreads();
    if (threadIdx.x < 32) {
        float t = (threadIdx.x < 8) ? ws[threadIdx.x] : 0.f;
#pragma unroll
        for (int o = 4; o; o >>= 1) t += __shfl_xor_sync(0xffffffffu, t, o);
        if (threadIdx.x == 0) ws[0] = t;
    }
    __syncthreads();
    const float rms = rsqrtf(ws[0] * (1.0f / D_MODEL) + EPS);

    float* orow = out + (size_t)row * D_MODEL;
#pragma unroll
    for (int i = 0; i < 4; i++) {
        int c = threadIdx.x + i * 256;
        orow[c] = v[i] * rms * g[c];
    }
}

// ---------------- SwiGLU ------------------------------------------------------
__global__ void __launch_bounds__(256)
swiglu(const float* __restrict__ yg, float* __restrict__ hbuf)
{
    int i = blockIdx.x * blockDim.x + threadIdx.x;     // over MTOT*FF
    int mrow = i >> 12;           // /4096
    int j = i & (FF - 1);
    const float* row = yg + (size_t)mrow * (2 * FF);
    float y = row[j];
    float gt = row[FF + j];
    float sig = 1.f / (1.f + expf(-gt));
    hbuf[i] = y * gt * sig;
}

// ---------------- host orchestration -----------------------------------------
extern "C" void kernel_launch(void* const* d_in, const int* in_sizes, int n_in,
                              void* d_out, int out_size)
{
    const float* x    = (const float*)d_in[0];
    const float* Wqkv = (const float*)d_in[1];
    const float* Wout = (const float*)d_in[2];
    const float* bout = (const float*)d_in[3];
    const float* W1   = (const float*)d_in[4];
    const float* W2   = (const float*)d_in[5];
    const float* g1   = (const float*)d_in[6];
    const float* g2   = (const float*)d_in[7];
    float* out = (float*)d_out;

    float *qkv, *Qp, *Kp, *Vp, *Op, *Ap, *x2, *yg, *hb, *y2;
    cudaGetSymbolAddress((void**)&qkv, g_qkv);
    cudaGetSymbolAddress((void**)&Qp,  g_q);
    cudaGetSymbolAddress((void**)&Kp,  g_k);
    cudaGetSymbolAddress((void**)&Vp,  g_v);
    cudaGetSymbolAddress((void**)&Op,  g_o);
    cudaGetSymbolAddress((void**)&Ap,  g_a);
    cudaGetSymbolAddress((void**)&x2,  g_x2);
    cudaGetSymbolAddress((void**)&yg,  g_yg);
    cudaGetSymbolAddress((void**)&hb,  g_hb);
    cudaGetSymbolAddress((void**)&y2,  g_y2);

    // 1) QKV = X @ Wqkv^T : [4096,1024] x [3072,1024]^T
    {
        dim3 grid((3 * D_MODEL) / BN, MTOT / BM);
        sgemm_nt<<<grid, 256>>>(x, Wqkv, qkv, MTOT, 3 * D_MODEL, D_MODEL);
    }

    // 2) RoPE + split
    {
        int total = BATCH * SEQ * NHEAD * 32;
        rope_split<<<total / 256, 256>>>(qkv, Qp, Kp, Vp);
    }

    // 3) banded attention
    {
        size_t smem = (size_t)(2 * KSPAN * KPAD + QTILE * KPAD + 8 * KSPAN) * sizeof(float);
        cudaFuncSetAttribute(attn_kernel, cudaFuncAttributeMaxDynamicSharedMemorySize, (int)smem);
        dim3 grid(SEQ / QTILE, BATCH * NHEAD);
        attn_kernel<<<grid, 256, smem>>>(Qp, Kp, Vp, Op);
    }

    // 4) A = O @ Wout^T
    {
        dim3 grid(D_MODEL / BN, MTOT / BM);
        sgemm_nt<<<grid, 256>>>(Op, Wout, Ap, MTOT, D_MODEL, D_MODEL);
    }

    // 5) x2 = rmsnorm(A + bout + ALPHA*x, g1)
    resid_rmsnorm<<<MTOT, 256>>>(Ap, bout, x, g1, x2);

    // 6) YG = x2 @ W1^T : [4096,1024] x [8192,1024]^T
    {
        dim3 grid((2 * FF) / BN, MTOT / BM);
        sgemm_nt<<<grid, 256>>>(x2, W1, yg, MTOT, 2 * FF, D_MODEL);
    }

    // 7) swiglu
    {
        size_t total = (size_t)MTOT * FF;
        swiglu<<<(int)(total / 256), 256>>>(yg, hb);
    }

    // 8) Y2 = H @ W2^T : [4096,4096] x [1024,4096]^T
    {
        dim3 grid(D_MODEL / BN, MTOT / BM);
        sgemm_nt<<<grid, 256>>>(hb, W2, y2, MTOT, D_MODEL, FF);
    }

    // 9) out = rmsnorm(Y2 + ALPHA*x2, g2)
    resid_rmsnorm<<<MTOT, 256>>>(y2, nullptr, x2, g2, out);
}

// round 3
// speedup vs baseline: 2.0906x; 2.0906x over previous
#include <cuda_runtime.h>
#include <cuda_bf16.h>
#include <math.h>
#include <stdint.h>

// ---------------- problem constants ----------------
#define D_MODEL 1024
#define NHEAD   16
#define HEAD_DIM 64
#define FF      4096
#define ALPHA   1.4142135f
#define EPS     1e-5f
#define BATCH   2
#define SEQ     2048
#define MTOT    (BATCH*SEQ)        // 4096 rows

// ---------------- scratch (device globals; no allocation allowed) ------------
__device__ float g_qkv[(size_t)MTOT * 3 * D_MODEL];
__device__ float g_q  [(size_t)BATCH * NHEAD * SEQ * HEAD_DIM];
__device__ float g_k  [(size_t)BATCH * NHEAD * SEQ * HEAD_DIM];
__device__ float g_v  [(size_t)BATCH * NHEAD * SEQ * HEAD_DIM];
__device__ float g_o  [(size_t)MTOT * D_MODEL];
__device__ float g_a  [(size_t)MTOT * D_MODEL];
__device__ float g_x2 [(size_t)MTOT * D_MODEL];
__device__ float g_yg [(size_t)MTOT * 2 * FF];
__device__ float g_y2 [(size_t)MTOT * D_MODEL];

// bf16 hi/lo split operands
__device__ __nv_bfloat16 g_xh [(size_t)MTOT * D_MODEL];
__device__ __nv_bfloat16 g_xl [(size_t)MTOT * D_MODEL];
__device__ __nv_bfloat16 g_oh [(size_t)MTOT * D_MODEL];
__device__ __nv_bfloat16 g_ol [(size_t)MTOT * D_MODEL];
__device__ __nv_bfloat16 g_x2h[(size_t)MTOT * D_MODEL];
__device__ __nv_bfloat16 g_x2l[(size_t)MTOT * D_MODEL];
__device__ __nv_bfloat16 g_hbh[(size_t)MTOT * FF];
__device__ __nv_bfloat16 g_hbl[(size_t)MTOT * FF];
__device__ __nv_bfloat16 g_wqh[(size_t)3*D_MODEL * D_MODEL];
__device__ __nv_bfloat16 g_wql[(size_t)3*D_MODEL * D_MODEL];
__device__ __nv_bfloat16 g_woh[(size_t)D_MODEL * D_MODEL];
__device__ __nv_bfloat16 g_wol[(size_t)D_MODEL * D_MODEL];
__device__ __nv_bfloat16 g_w1h[(size_t)2*FF * D_MODEL];
__device__ __nv_bfloat16 g_w1l[(size_t)2*FF * D_MODEL];
__device__ __nv_bfloat16 g_w2h[(size_t)D_MODEL * FF];
__device__ __nv_bfloat16 g_w2l[(size_t)D_MODEL * FF];

// ---------------- PTX helpers -------------------------------------------------
__device__ __forceinline__ uint32_t smem_u32(const void* p) {
    uint32_t a;
    asm("{ .reg .u64 t; cvta.to.shared.u64 t, %1; cvt.u32.u64 %0, t; }" : "=r"(a) : "l"(p));
    return a;
}

#define CP_ASYNC16(dst, src) \
    asm volatile("cp.async.cg.shared.global [%0], [%1], 16;" :: "r"(dst), "l"(src) : "memory")
#define CP_COMMIT() asm volatile("cp.async.commit_group;" ::: "memory")
#define CP_WAIT1()  asm volatile("cp.async.wait_group 1;" ::: "memory")

#define LDSM_X4(r0, r1, r2, r3, addr) \
    asm volatile("ldmatrix.sync.aligned.m8n8.x4.shared.b16 {%0,%1,%2,%3}, [%4];" \
        : "=r"(r0), "=r"(r1), "=r"(r2), "=r"(r3) : "r"(addr))

#define MMA_BF16(d, a, b0v, b1v) \
    asm volatile("mma.sync.aligned.m16n8k16.row.col.f32.bf16.bf16.f32 " \
        "{%0,%1,%2,%3}, {%4,%5,%6,%7}, {%8,%9}, {%0,%1,%2,%3};" \
        : "+f"((d)[0]), "+f"((d)[1]), "+f"((d)[2]), "+f"((d)[3]) \
        : "r"((a)[0]), "r"((a)[1]), "r"((a)[2]), "r"((a)[3]), "r"(b0v), "r"(b1v))

// ---------------- HMMA GEMM: C[M,N] = (Ah+Al)[M,K] * ((Bh+Bl)[N,K])^T --------
// bf16x3: Ah*Bh + Al*Bh + Ah*Bl, fp32 accumulation. BM=BN=128, BK=32, 3 stages.
#define GK 32
#define GSTG 3
#define TILEB (128*64)               // bytes per operand tile (128 rows x 64B)

__global__ void __launch_bounds__(256, 2)
gemm_mma(const __nv_bfloat16* __restrict__ Ah, const __nv_bfloat16* __restrict__ Al,
         const __nv_bfloat16* __restrict__ Bh, const __nv_bfloat16* __restrict__ Bl,
         float* __restrict__ C, int M, int N, int K)
{
    __shared__ __align__(128) char smA[GSTG][TILEB];
    __shared__ __align__(128) char smB[GSTG][TILEB];

    const int tid  = threadIdx.x;
    const int lane = tid & 31;
    const int wid  = tid >> 5;
    const int wm   = wid >> 2;           // 0..1
    const int wn   = wid & 3;            // 0..3
    const int bm   = blockIdx.y * 128;
    const int bn   = blockIdx.x * 128;

    const int NK    = K / GK;
    const int total = 3 * NK;

    const uint32_t sA = smem_u32(smA);
    const uint32_t sB = smem_u32(smB);

    // per-thread load mapping: chunks (row, cc) and (row+64, cc)
    const int lrow = tid >> 2;           // 0..63
    const int lcc  = tid & 3;            // 0..3

    auto load_stage = [&](int s, int c) {
        const int kc = (c < NK) ? c : ((c < 2 * NK) ? c - NK : c - 2 * NK);
        const __nv_bfloat16* Ap = (c >= NK && c < 2 * NK) ? Al : Ah;
        const __nv_bfloat16* Bp = (c >= 2 * NK) ? Bl : Bh;
#pragma unroll
        for (int half = 0; half < 2; half++) {
            const int row = lrow + half * 64;
            const uint32_t swz = (uint32_t)(row * 64 + ((lcc ^ ((row >> 1) & 3)) << 4));
            const __nv_bfloat16* ag = Ap + (size_t)(bm + row) * K + kc * GK + lcc * 8;
            CP_ASYNC16(sA + s * TILEB + swz, ag);
            const __nv_bfloat16* bg = Bp + (size_t)(bn + row) * K + kc * GK + lcc * 8;
            CP_ASYNC16(sB + s * TILEB + swz, bg);
        }
    };

    float acc[4][4][4];
#pragma unroll
    for (int mi = 0; mi < 4; mi++)
#pragma unroll
        for (int ni = 0; ni < 4; ni++)
#pragma unroll
            for (int r = 0; r < 4; r++) acc[mi][ni][r] = 0.f;

    // prologue
    load_stage(0, 0); CP_COMMIT();
    load_stage(1, 1); CP_COMMIT();

    const int m_idx = lane >> 3;         // 0..3 (ldmatrix sub-matrix)

    for (int c = 0; c < total; c++) {
        CP_WAIT1();
        __syncthreads();
        if (c + 2 < total) load_stage((c + 2) % GSTG, c + 2);
        CP_COMMIT();

        const uint32_t Ab = sA + (c % GSTG) * TILEB;
        const uint32_t Bb = sB + (c % GSTG) * TILEB;

#pragma unroll
        for (int ks = 0; ks < 2; ks++) {
            uint32_t af[4][4];
#pragma unroll
            for (int mi = 0; mi < 4; mi++) {
                const int row = wm * 64 + mi * 16 + (lane & 7) + ((m_idx & 1) << 3);
                const int cch = 2 * ks + (m_idx >> 1);
                const uint32_t addr = Ab + row * 64 + ((cch ^ ((row >> 1) & 3)) << 4);
                LDSM_X4(af[mi][0], af[mi][1], af[mi][2], af[mi][3], addr);
            }
            uint32_t bf_[2][4];
#pragma unroll
            for (int pi = 0; pi < 2; pi++) {
                const int nrow = wn * 32 + pi * 16 + (lane & 7) + ((m_idx >> 1) << 3);
                const int cch = 2 * ks + (m_idx & 1);
                const uint32_t addr = Bb + nrow * 64 + ((cch ^ ((nrow >> 1) & 3)) << 4);
                LDSM_X4(bf_[pi][0], bf_[pi][1], bf_[pi][2], bf_[pi][3], addr);
            }
#pragma unroll
            for (int mi = 0; mi < 4; mi++)
#pragma unroll
                for (int ni = 0; ni < 4; ni++)
                    MMA_BF16(acc[mi][ni], af[mi],
                             bf_[ni >> 1][(ni & 1) * 2], bf_[ni >> 1][(ni & 1) * 2 + 1]);
        }
        // next iteration's __syncthreads protects stage reuse
    }

    // epilogue: direct fp32 stores
#pragma unroll
    for (int mi = 0; mi < 4; mi++) {
        const int row0 = bm + wm * 64 + mi * 16 + (lane >> 2);
#pragma unroll
        for (int ni = 0; ni < 4; ni++) {
            const int col = bn + wn * 32 + ni * 8 + (lane & 3) * 2;
            *(float2*)(C + (size_t)row0 * N + col) = make_float2(acc[mi][ni][0], acc[mi][ni][1]);
            *(float2*)(C + (size_t)(row0 + 8) * N + col) = make_float2(acc[mi][ni][2], acc[mi][ni][3]);
        }
    }
}

// ---------------- fp32 -> bf16 hi/lo split ------------------------------------
__device__ __forceinline__ void split2(float x, __nv_bfloat16& h, __nv_bfloat16& l) {
    h = __float2bfloat16_rn(x);
    l = __float2bfloat16_rn(x - __bfloat162float(h));
}

__global__ void __launch_bounds__(256)
split_bf16(const float* __restrict__ X, __nv_bfloat16* __restrict__ H,
           __nv_bfloat16* __restrict__ L, int n4)
{
    int i = blockIdx.x * blockDim.x + threadIdx.x;
    if (i >= n4) return;
    float4 v = ((const float4*)X)[i];
    __nv_bfloat16 h[4], l[4];
    split2(v.x, h[0], l[0]); split2(v.y, h[1], l[1]);
    split2(v.z, h[2], l[2]); split2(v.w, h[3], l[3]);
    ((uint2*)H)[i] = *(uint2*)h;
    ((uint2*)L)[i] = *(uint2*)l;
}

// ---------------- RoPE + split into [B,H,T,Dh] -------------------------------
__global__ void __launch_bounds__(256)
rope_split(const float* __restrict__ qkv,
           float* __restrict__ Q, float* __restrict__ K, float* __restrict__ V)
{
    int i = blockIdx.x * blockDim.x + threadIdx.x;
    int d = i & 31;
    int h = (i >> 5) & (NHEAD - 1);
    int t = (i >> 9) & (SEQ - 1);
    int b = i >> (9 + 11);
    if (b >= BATCH) return;

    const float* base = qkv + ((size_t)(b * SEQ + t) * 3) * D_MODEL + h * HEAD_DIM;
    float q1 = base[d],               q2 = base[d + 32];
    float k1 = base[D_MODEL + d],     k2 = base[D_MODEL + d + 32];
    float v1 = base[2 * D_MODEL + d], v2 = base[2 * D_MODEL + d + 32];

    float inv = powf(10000.0f, -(float)d / 32.0f);
    float ang = (float)t * inv;
    float c = cosf(ang), s = sinf(ang);

    size_t o = (((size_t)(b * NHEAD + h) * SEQ) + t) * HEAD_DIM;
    Q[o + d]      = q1 * c - q2 * s;
    Q[o + d + 32] = q2 * c + q1 * s;
    K[o + d]      = k1 * c - k2 * s;
    K[o + d + 32] = k2 * c + k1 * s;
    V[o + d]      = v1;
    V[o + d + 32] = v2;
}

// ---------------- banded attention -------------------------------------------
#define QTILE 64
#define KSPAN 320
#define KPAD  68

__global__ void __launch_bounds__(256)
attn_kernel(const float* __restrict__ Q, const float* __restrict__ K,
            const float* __restrict__ V, float* __restrict__ O)
{
    extern __shared__ float sm[];
    float* Ks = sm;
    float* Vs = Ks + KSPAN * KPAD;
    float* Qs = Vs + KSPAN * KPAD;
    float* Pr = Qs + QTILE * KPAD;

    const int bh = blockIdx.y;
    const int q0 = blockIdx.x * QTILE;
    const int klo = max(0, q0 - 127);
    const int khi = min(SEQ - 1, q0 + QTILE - 1 + 128);
    const int nk = khi - klo + 1;

    const int tid = threadIdx.x;
    const float* Kb = K + (size_t)bh * SEQ * HEAD_DIM;
    const float* Vb = V + (size_t)bh * SEQ * HEAD_DIM;
    const float* Qb = Q + (size_t)bh * SEQ * HEAD_DIM;

    for (int i = tid; i < nk * HEAD_DIM; i += 256) {
        int r = i >> 6, d = i & 63;
        Ks[r * KPAD + d] = Kb[(size_t)(klo + r) * HEAD_DIM + d];
        Vs[r * KPAD + d] = Vb[(size_t)(klo + r) * HEAD_DIM + d];
    }
    for (int i = tid; i < QTILE * HEAD_DIM; i += 256) {
        int r = i >> 6, d = i & 63;
        Qs[r * KPAD + d] = Qb[(size_t)(q0 + r) * HEAD_DIM + d];
    }
    __syncthreads();

    const int w = tid >> 5, lane = tid & 31;
    float* P = Pr + w * KSPAN;
    const int b = bh / NHEAD, h = bh % NHEAD;

    for (int j = 0; j < 8; j++) {
        const int ql = w * 8 + j;
        const int q = q0 + ql;
        const int lo = max(0, q - 127) - klo;
        const int hi = min(SEQ - 1, q + 128) - klo;

        float4 qv[16];
        const float4* qr4 = (const float4*)&Qs[ql * KPAD];
#pragma unroll
        for (int d = 0; d < 16; d++) qv[d] = qr4[d];

        float m = -INFINITY;
        for (int kk = lo + lane; kk <= hi; kk += 32) {
            const float4* kr4 = (const float4*)&Ks[kk * KPAD];
            float s = 0.f;
#pragma unroll
            for (int d = 0; d < 16; d++) {
                float4 kvv = kr4[d];
                s += qv[d].x * kvv.x + qv[d].y * kvv.y + qv[d].z * kvv.z + qv[d].w * kvv.w;
            }
            s *= 0.125f;
            P[kk] = s;
            m = fmaxf(m, s);
        }
#pragma unroll
        for (int o = 16; o; o >>= 1) m = fmaxf(m, __shfl_xor_sync(0xffffffffu, m, o));

        float sum = 0.f;
        for (int kk = lo + lane; kk <= hi; kk += 32) {
            float e = expf(P[kk] - m);
            P[kk] = e;
            sum += e;
        }
#pragma unroll
        for (int o = 16; o; o >>= 1) sum += __shfl_xor_sync(0xffffffffu, sum, o);
        const float invs = 1.f / sum;
        __syncwarp();

        float2 acc = make_float2(0.f, 0.f);
        for (int kk = lo; kk <= hi; kk++) {
            float p = P[kk];
            float2 vv = *(const float2*)&Vs[kk * KPAD + 2 * lane];
            acc.x += p * vv.x;
            acc.y += p * vv.y;
        }
        float* orow = O + ((size_t)(b * SEQ + q)) * D_MODEL + h * HEAD_DIM;
        ((float2*)orow)[lane] = make_float2(acc.x * invs, acc.y * invs);
        __syncwarp();
    }
}

// ---------------- residual + (opt bias) + RMSNorm (+opt bf16 split out) ------
__global__ void __launch_bounds__(256)
resid_rmsnorm(const float* __restrict__ A, const float* __restrict__ bias,
              const float* __restrict__ R, const float* __restrict__ g,
              float* __restrict__ out,
              __nv_bfloat16* __restrict__ outH, __nv_bfloat16* __restrict__ outL)
{
    const int row = blockIdx.x;
    const float* a = A + (size_t)row * D_MODEL;
    const float* r = R + (size_t)row * D_MODEL;

    float v[4];
    float ss = 0.f;
#pragma unroll
    for (int i = 0; i < 4; i++) {
        int c = threadIdx.x + i * 256;
        float x = a[c] + ALPHA * r[c];
        if (bias) x += bias[c];
        v[i] = x;
        ss += x * x;
    }
#pragma unroll
    for (int o = 16; o; o >>= 1) ss += __shfl_xor_sync(0xffffffffu, ss, o);

    __shared__ float ws[8];
    if ((threadIdx.x & 31) == 0) ws[threadIdx.x >> 5] = ss;
    __syncthreads();
    if (threadIdx.x < 32) {
        float t = (threadIdx.x < 8) ? ws[threadIdx.x] : 0.f;
#pragma unroll
        for (int o = 4; o; o >>= 1) t += __shfl_xor_sync(0xffffffffu, t, o);
        if (threadIdx.x == 0) ws[0] = t;
    }
    __syncthreads();
    const float rms = rsqrtf(ws[0] * (1.0f / D_MODEL) + EPS);

    float* orow = out + (size_t)row * D_MODEL;
#pragma unroll
    for (int i = 0; i < 4; i++) {
        int c = threadIdx.x + i * 256;
        float y = v[i] * rms * g[c];
        orow[c] = y;
        if (outH) {
            __nv_bfloat16 h, l;
            split2(y, h, l);
            outH[(size_t)row * D_MODEL + c] = h;
            outL[(size_t)row * D_MODEL + c] = l;
        }
    }
}

// ---------------- SwiGLU -> bf16 hi/lo ----------------------------------------
__global__ void __launch_bounds__(256)
swiglu(const float* __restrict__ yg, __nv_bfloat16* __restrict__ H,
       __nv_bfloat16* __restrict__ L)
{
    int i = blockIdx.x * blockDim.x + threadIdx.x;     // over MTOT*FF
    int mrow = i >> 12;
    int j = i & (FF - 1);
    const float* row = yg + (size_t)mrow * (2 * FF);
    float y = row[j];
    float gt = row[FF + j];
    float sig = 1.f / (1.f + expf(-gt));
    float hv = y * gt * sig;
    __nv_bfloat16 h, l;
    split2(hv, h, l);
    H[i] = h;
    L[i] = l;
}

// ---------------- host orchestration -----------------------------------------
static void launch_gemm(const __nv_bfloat16* Ah, const __nv_bfloat16* Al,
                        const __nv_bfloat16* Bh, const __nv_bfloat16* Bl,
                        float* C, int M, int N, int K)
{
    dim3 grid(N / 128, M / 128);
    gemm_mma<<<grid, 256>>>(Ah, Al, Bh, Bl, C, M, N, K);
}

extern "C" void kernel_launch(void* const* d_in, const int* in_sizes, int n_in,
                              void* d_out, int out_size)
{
    const float* x    = (const float*)d_in[0];
    const float* Wqkv = (const float*)d_in[1];
    const float* Wout = (const float*)d_in[2];
    const float* bout = (const float*)d_in[3];
    const float* W1   = (const float*)d_in[4];
    const float* W2   = (const float*)d_in[5];
    const float* g1   = (const float*)d_in[6];
    const float* g2   = (const float*)d_in[7];
    float* out = (float*)d_out;

    float *qkv, *Qp, *Kp, *Vp, *Op, *Ap, *x2, *yg, *y2;
    cudaGetSymbolAddress((void**)&qkv, g_qkv);
    cudaGetSymbolAddress((void**)&Qp,  g_q);
    cudaGetSymbolAddress((void**)&Kp,  g_k);
    cudaGetSymbolAddress((void**)&Vp,  g_v);
    cudaGetSymbolAddress((void**)&Op,  g_o);
    cudaGetSymbolAddress((void**)&Ap,  g_a);
    cudaGetSymbolAddress((void**)&x2,  g_x2);
    cudaGetSymbolAddress((void**)&yg,  g_yg);
    cudaGetSymbolAddress((void**)&y2,  g_y2);

    __nv_bfloat16 *xh,*xl,*oh,*ol,*x2h,*x2l,*hbh,*hbl,*wqh,*wql,*woh,*wol,*w1h,*w1l,*w2h,*w2l;
    cudaGetSymbolAddress((void**)&xh,  g_xh);  cudaGetSymbolAddress((void**)&xl,  g_xl);
    cudaGetSymbolAddress((void**)&oh,  g_oh);  cudaGetSymbolAddress((void**)&ol,  g_ol);
    cudaGetSymbolAddress((void**)&x2h, g_x2h); cudaGetSymbolAddress((void**)&x2l, g_x2l);
    cudaGetSymbolAddress((void**)&hbh, g_hbh); cudaGetSymbolAddress((void**)&hbl, g_hbl);
    cudaGetSymbolAddress((void**)&wqh, g_wqh); cudaGetSymbolAddress((void**)&wql, g_wql);
    cudaGetSymbolAddress((void**)&woh, g_woh); cudaGetSymbolAddress((void**)&wol, g_wol);
    cudaGetSymbolAddress((void**)&w1h, g_w1h); cudaGetSymbolAddress((void**)&w1l, g_w1l);
    cudaGetSymbolAddress((void**)&w2h, g_w2h); cudaGetSymbolAddress((void**)&w2l, g_w2l);

    // ---- operand splits (weights + input) ----
    {
        int n;
        n = MTOT * D_MODEL / 4;           split_bf16<<<(n+255)/256, 256>>>(x,    xh,  xl,  n);
        n = 3*D_MODEL * D_MODEL / 4;      split_bf16<<<(n+255)/256, 256>>>(Wqkv, wqh, wql, n);
        n = D_MODEL * D_MODEL / 4;        split_bf16<<<(n+255)/256, 256>>>(Wout, woh, wol, n);
        n = 2*FF * D_MODEL / 4;           split_bf16<<<(n+255)/256, 256>>>(W1,   w1h, w1l, n);
        n = D_MODEL * FF / 4;             split_bf16<<<(n+255)/256, 256>>>(W2,   w2h, w2l, n);
    }

    // 1) QKV = X @ Wqkv^T
    launch_gemm(xh, xl, wqh, wql, qkv, MTOT, 3 * D_MODEL, D_MODEL);

    // 2) RoPE + split heads
    {
        int total = BATCH * SEQ * NHEAD * 32;
        rope_split<<<total / 256, 256>>>(qkv, Qp, Kp, Vp);
    }

    // 3) banded attention
    {
        size_t smem = (size_t)(2 * KSPAN * KPAD + QTILE * KPAD + 8 * KSPAN) * sizeof(float);
        cudaFuncSetAttribute(attn_kernel, cudaFuncAttributeMaxDynamicSharedMemorySize, (int)smem);
        dim3 grid(SEQ / QTILE, BATCH * NHEAD);
        attn_kernel<<<grid, 256, smem>>>(Qp, Kp, Vp, Op);
    }

    // 3b) split O
    {
        int n = MTOT * D_MODEL / 4;
        split_bf16<<<(n+255)/256, 256>>>(Op, oh, ol, n);
    }

    // 4) A = O @ Wout^T
    launch_gemm(oh, ol, woh, wol, Ap, MTOT, D_MODEL, D_MODEL);

    // 5) x2 = rmsnorm(A + bout + ALPHA*x, g1) (+ bf16 split)
    resid_rmsnorm<<<MTOT, 256>>>(Ap, bout, x, g1, x2, x2h, x2l);

    // 6) YG = x2 @ W1^T
    launch_gemm(x2h, x2l, w1h, w1l, yg, MTOT, 2 * FF, D_MODEL);

    // 7) swiglu -> hb (bf16 split)
    {
        size_t total = (size_t)MTOT * FF;
        swiglu<<<(int)(total / 256), 256>>>(yg, hbh, hbl);
    }

    // 8) Y2 = H @ W2^T   (K = FF)
    launch_gemm(hbh, hbl, w2h, w2l, y2, MTOT, D_MODEL, FF);

    // 9) out = rmsnorm(Y2 + ALPHA*x2, g2)
    resid_rmsnorm<<<MTOT, 256>>>(y2, nullptr, x2, g2, out, nullptr, nullptr);
}

// round 4
// speedup vs baseline: 2.3347x; 1.1168x over previous
#include <cuda_runtime.h>
#include <cuda_bf16.h>
#include <math.h>
#include <stdint.h>

// ---------------- problem constants ----------------
#define D_MODEL 1024
#define NHEAD   16
#define HEAD_DIM 64
#define FF      4096
#define ALPHA   1.4142135f
#define EPS     1e-5f
#define BATCH   2
#define SEQ     2048
#define MTOT    (BATCH*SEQ)        // 4096 rows

// ---------------- scratch (device globals; no allocation allowed) ------------
__device__ float g_qkv[(size_t)MTOT * 3 * D_MODEL];
__device__ float g_q  [(size_t)BATCH * NHEAD * SEQ * HEAD_DIM];
__device__ float g_k  [(size_t)BATCH * NHEAD * SEQ * HEAD_DIM];
__device__ float g_v  [(size_t)BATCH * NHEAD * SEQ * HEAD_DIM];
__device__ float g_a  [(size_t)MTOT * D_MODEL];
__device__ float g_x2 [(size_t)MTOT * D_MODEL];
__device__ float g_y2 [(size_t)MTOT * D_MODEL];

// bf16 hi/lo split operands
__device__ __nv_bfloat16 g_xh [(size_t)MTOT * D_MODEL];
__device__ __nv_bfloat16 g_xl [(size_t)MTOT * D_MODEL];
__device__ __nv_bfloat16 g_oh [(size_t)MTOT * D_MODEL];
__device__ __nv_bfloat16 g_ol [(size_t)MTOT * D_MODEL];
__device__ __nv_bfloat16 g_x2h[(size_t)MTOT * D_MODEL];
__device__ __nv_bfloat16 g_x2l[(size_t)MTOT * D_MODEL];
__device__ __nv_bfloat16 g_hbh[(size_t)MTOT * FF];
__device__ __nv_bfloat16 g_hbl[(size_t)MTOT * FF];
__device__ __nv_bfloat16 g_wqh[(size_t)3*D_MODEL * D_MODEL];
__device__ __nv_bfloat16 g_wql[(size_t)3*D_MODEL * D_MODEL];
__device__ __nv_bfloat16 g_woh[(size_t)D_MODEL * D_MODEL];
__device__ __nv_bfloat16 g_wol[(size_t)D_MODEL * D_MODEL];
__device__ __nv_bfloat16 g_w1h[(size_t)2*FF * D_MODEL];   // permuted y/gate interleave
__device__ __nv_bfloat16 g_w1l[(size_t)2*FF * D_MODEL];
__device__ __nv_bfloat16 g_w2h[(size_t)D_MODEL * FF];
__device__ __nv_bfloat16 g_w2l[(size_t)D_MODEL * FF];

// ---------------- PTX helpers -------------------------------------------------
__device__ __forceinline__ uint32_t smem_u32(const void* p) {
    uint32_t a;
    asm("{ .reg .u64 t; cvta.to.shared.u64 t, %1; cvt.u32.u64 %0, t; }" : "=r"(a) : "l"(p));
    return a;
}

#define CP_ASYNC16(dst, src) \
    asm volatile("cp.async.cg.shared.global [%0], [%1], 16;" :: "r"(dst), "l"(src) : "memory")
#define CP_COMMIT() asm volatile("cp.async.commit_group;" ::: "memory")
#define CP_WAIT1()  asm volatile("cp.async.wait_group 1;" ::: "memory")

#define LDSM_X4(r0, r1, r2, r3, addr) \
    asm volatile("ldmatrix.sync.aligned.m8n8.x4.shared.b16 {%0,%1,%2,%3}, [%4];" \
        : "=r"(r0), "=r"(r1), "=r"(r2), "=r"(r3) : "r"(addr))

#define MMA_BF16(d, a, b0v, b1v) \
    asm volatile("mma.sync.aligned.m16n8k16.row.col.f32.bf16.bf16.f32 " \
        "{%0,%1,%2,%3}, {%4,%5,%6,%7}, {%8,%9}, {%0,%1,%2,%3};" \
        : "+f"((d)[0]), "+f"((d)[1]), "+f"((d)[2]), "+f"((d)[3]) \
        : "r"((a)[0]), "r"((a)[1]), "r"((a)[2]), "r"((a)[3]), "r"(b0v), "r"(b1v))

__device__ __forceinline__ void split2(float x, __nv_bfloat16& h, __nv_bfloat16& l) {
    h = __float2bfloat16_rn(x);
    l = __float2bfloat16_rn(x - __bfloat162float(h));
}

// ---------------- HMMA GEMM, term-merged bf16x3 -------------------------------
// C[M,N] = (Ah+Al)[M,K] * ((Bh+Bl)[N,K])^T  via Ah*Bh + Al*Bh + Ah*Bl.
// BM=256, BN=128, BK=32, 3 stages. Each stage holds Ah,Al,Bh,Bl tiles.
// MODE 0: write fp32 C.  MODE 1: cols are (y,gate) pairs -> swiglu -> bf16 h/l.
#define GBM 256
#define GBN 128
#define GK  32
#define GSTG 3
#define TA  (GBM*64)                 // 16 KB: one A tile (256 rows x 64B)
#define TB  (GBN*64)                 // 8 KB: one B tile
#define STAGE_B (2*TA + 2*TB)        // 48 KB per stage

template<int MODE>
__global__ void __launch_bounds__(256, 1)
gemm_mma(const __nv_bfloat16* __restrict__ Ah, const __nv_bfloat16* __restrict__ Al,
         const __nv_bfloat16* __restrict__ Bh, const __nv_bfloat16* __restrict__ Bl,
         float* __restrict__ C,
         __nv_bfloat16* __restrict__ Ho, __nv_bfloat16* __restrict__ Lo,
         int M, int N, int K)
{
    extern __shared__ __align__(128) char smem[];

    const int tid  = threadIdx.x;
    const int lane = tid & 31;
    const int wid  = tid >> 5;
    const int wm   = wid >> 1;           // 0..3
    const int wn   = wid & 1;            // 0..1
    const int bm   = blockIdx.y * GBM;
    const int bn   = blockIdx.x * GBN;

    const int NK = K / GK;
    const uint32_t sbase = smem_u32(smem);

    const int lrow = tid >> 2;           // 0..63
    const int lcc  = tid & 3;            // 0..3

    auto load_stage = [&](int s, int kc) {
        const uint32_t st = sbase + s * STAGE_B;
#pragma unroll
        for (int half = 0; half < 4; half++) {
            const int row = lrow + half * 64;
            const uint32_t swz = (uint32_t)(row * 64 + ((lcc ^ ((row >> 1) & 3)) << 4));
            CP_ASYNC16(st + swz,       Ah + (size_t)(bm + row) * K + kc * GK + lcc * 8);
            CP_ASYNC16(st + TA + swz,  Al + (size_t)(bm + row) * K + kc * GK + lcc * 8);
        }
#pragma unroll
        for (int half = 0; half < 2; half++) {
            const int row = lrow + half * 64;
            const uint32_t swz = (uint32_t)(row * 64 + ((lcc ^ ((row >> 1) & 3)) << 4));
            CP_ASYNC16(st + 2*TA + swz,      Bh + (size_t)(bn + row) * K + kc * GK + lcc * 8);
            CP_ASYNC16(st + 2*TA + TB + swz, Bl + (size_t)(bn + row) * K + kc * GK + lcc * 8);
        }
    };

    float acc[4][8][4];
#pragma unroll
    for (int mi = 0; mi < 4; mi++)
#pragma unroll
        for (int ni = 0; ni < 8; ni++)
#pragma unroll
            for (int r = 0; r < 4; r++) acc[mi][ni][r] = 0.f;

    load_stage(0, 0); CP_COMMIT();
    load_stage(1, 1); CP_COMMIT();

    const int m_idx = lane >> 3;

    for (int c = 0; c < NK; c++) {
        CP_WAIT1();
        __syncthreads();
        if (c + 2 < NK) load_stage((c + 2) % GSTG, c + 2);
        CP_COMMIT();

        const uint32_t st = sbase + (c % GSTG) * STAGE_B;
        const uint32_t Ahb = st, Alb = st + TA, Bhb = st + 2*TA, Blb = st + 2*TA + TB;

#pragma unroll
        for (int ks = 0; ks < 2; ks++) {
            uint32_t afh[4][4], afl[4][4], bfh[4][4], bfl[4][4];
#pragma unroll
            for (int mi = 0; mi < 4; mi++) {
                const int row = wm * 64 + mi * 16 + (lane & 7) + ((m_idx & 1) << 3);
                const int cch = 2 * ks + (m_idx >> 1);
                const uint32_t off = (uint32_t)(row * 64 + ((cch ^ ((row >> 1) & 3)) << 4));
                LDSM_X4(afh[mi][0], afh[mi][1], afh[mi][2], afh[mi][3], Ahb + off);
                LDSM_X4(afl[mi][0], afl[mi][1], afl[mi][2], afl[mi][3], Alb + off);
            }
#pragma unroll
            for (int pi = 0; pi < 4; pi++) {
                const int nrow = wn * 64 + pi * 16 + (lane & 7) + ((m_idx >> 1) << 3);
                const int cch = 2 * ks + (m_idx & 1);
                const uint32_t off = (uint32_t)(nrow * 64 + ((cch ^ ((nrow >> 1) & 3)) << 4));
                LDSM_X4(bfh[pi][0], bfh[pi][1], bfh[pi][2], bfh[pi][3], Bhb + off);
                LDSM_X4(bfl[pi][0], bfl[pi][1], bfl[pi][2], bfl[pi][3], Blb + off);
            }
#pragma unroll
            for (int mi = 0; mi < 4; mi++)
#pragma unroll
                for (int ni = 0; ni < 8; ni++) {
                    const int pi = ni >> 1, bo = (ni & 1) * 2;
                    MMA_BF16(acc[mi][ni], afh[mi], bfh[pi][bo], bfh[pi][bo + 1]);
                    MMA_BF16(acc[mi][ni], afl[mi], bfh[pi][bo], bfh[pi][bo + 1]);
                    MMA_BF16(acc[mi][ni], afh[mi], bfl[pi][bo], bfl[pi][bo + 1]);
                }
        }
    }

    // epilogue
#pragma unroll
    for (int mi = 0; mi < 4; mi++) {
        const int row0 = bm + wm * 64 + mi * 16 + (lane >> 2);
#pragma unroll
        for (int ni = 0; ni < 8; ni++) {
            const int col = bn + wn * 64 + ni * 8 + (lane & 3) * 2;
            if (MODE == 0) {
                *(float2*)(C + (size_t)row0 * N + col)      = make_float2(acc[mi][ni][0], acc[mi][ni][1]);
                *(float2*)(C + (size_t)(row0 + 8) * N + col) = make_float2(acc[mi][ni][2], acc[mi][ni][3]);
            } else {
                const int Nout = N >> 1;
                const int j = col >> 1;
                float y0 = acc[mi][ni][0], gt0 = acc[mi][ni][1];
                float y1 = acc[mi][ni][2], gt1 = acc[mi][ni][3];
                float h0 = y0 * gt0 / (1.f + expf(-gt0));
                float h1 = y1 * gt1 / (1.f + expf(-gt1));
                __nv_bfloat16 hh, ll;
                split2(h0, hh, ll);
                Ho[(size_t)row0 * Nout + j] = hh;
                Lo[(size_t)row0 * Nout + j] = ll;
                split2(h1, hh, ll);
                Ho[(size_t)(row0 + 8) * Nout + j] = hh;
                Lo[(size_t)(row0 + 8) * Nout + j] = ll;
            }
        }
    }
}

// ---------------- fp32 -> bf16 hi/lo split ------------------------------------
__global__ void __launch_bounds__(256)
split_bf16(const float* __restrict__ X, __nv_bfloat16* __restrict__ H,
           __nv_bfloat16* __restrict__ L, int n4)
{
    int i = blockIdx.x * blockDim.x + threadIdx.x;
    if (i >= n4) return;
    float4 v = ((const float4*)X)[i];
    __nv_bfloat16 h[4], l[4];
    split2(v.x, h[0], l[0]); split2(v.y, h[1], l[1]);
    split2(v.z, h[2], l[2]); split2(v.w, h[3], l[3]);
    ((uint2*)H)[i] = *(uint2*)h;
    ((uint2*)L)[i] = *(uint2*)l;
}

// W1 split with y/gate row interleave: perm(j) = 2j (y), perm(FF+j) = 2j+1 (gate)
__global__ void __launch_bounds__(256)
split_bf16_w1(const float* __restrict__ X, __nv_bfloat16* __restrict__ H,
              __nv_bfloat16* __restrict__ L, int n4)
{
    int i = blockIdx.x * blockDim.x + threadIdx.x;
    if (i >= n4) return;
    int flat = i * 4;
    int row = flat >> 10;               // /D_MODEL
    int col = flat & (D_MODEL - 1);
    int prow = (row < FF) ? (2 * row) : (2 * (row - FF) + 1);
    float4 v = ((const float4*)X)[i];
    __nv_bfloat16 h[4], l[4];
    split2(v.x, h[0], l[0]); split2(v.y, h[1], l[1]);
    split2(v.z, h[2], l[2]); split2(v.w, h[3], l[3]);
    size_t o = ((size_t)prow * D_MODEL + col) >> 2;
    ((uint2*)H)[o] = *(uint2*)h;
    ((uint2*)L)[o] = *(uint2*)l;
}

// ---------------- RoPE + split into [B,H,T,Dh] -------------------------------
__global__ void __launch_bounds__(256)
rope_split(const float* __restrict__ qkv,
           float* __restrict__ Q, float* __restrict__ K, float* __restrict__ V)
{
    int i = blockIdx.x * blockDim.x + threadIdx.x;
    int d = i & 31;
    int h = (i >> 5) & (NHEAD - 1);
    int t = (i >> 9) & (SEQ - 1);
    int b = i >> (9 + 11);
    if (b >= BATCH) return;

    const float* base = qkv + ((size_t)(b * SEQ + t) * 3) * D_MODEL + h * HEAD_DIM;
    float q1 = base[d],               q2 = base[d + 32];
    float k1 = base[D_MODEL + d],     k2 = base[D_MODEL + d + 32];
    float v1 = base[2 * D_MODEL + d], v2 = base[2 * D_MODEL + d + 32];

    float inv = powf(10000.0f, -(float)d / 32.0f);
    float ang = (float)t * inv;
    float c = cosf(ang), s = sinf(ang);

    size_t o = (((size_t)(b * NHEAD + h) * SEQ) + t) * HEAD_DIM;
    Q[o + d]      = q1 * c - q2 * s;
    Q[o + d + 32] = q2 * c + q1 * s;
    K[o + d]      = k1 * c - k2 * s;
    K[o + d + 32] = k2 * c + k1 * s;
    V[o + d]      = v1;
    V[o + d + 32] = v2;
}

// ---------------- banded attention (writes bf16 hi/lo O) ----------------------
#define QTILE 64
#define KSPAN 320
#define KPAD  68

__global__ void __launch_bounds__(256)
attn_kernel(const float* __restrict__ Q, const float* __restrict__ K,
            const float* __restrict__ V,
            __nv_bfloat16* __restrict__ OH, __nv_bfloat16* __restrict__ OL)
{
    extern __shared__ float sm[];
    float* Ks = sm;
    float* Vs = Ks + KSPAN * KPAD;
    float* Qs = Vs + KSPAN * KPAD;
    float* Pr = Qs + QTILE * KPAD;

    const int bh = blockIdx.y;
    const int q0 = blockIdx.x * QTILE;
    const int klo = max(0, q0 - 127);
    const int khi = min(SEQ - 1, q0 + QTILE - 1 + 128);
    const int nk = khi - klo + 1;

    const int tid = threadIdx.x;
    const float* Kb = K + (size_t)bh * SEQ * HEAD_DIM;
    const float* Vb = V + (size_t)bh * SEQ * HEAD_DIM;
    const float* Qb = Q + (size_t)bh * SEQ * HEAD_DIM;

    for (int i = tid; i < nk * HEAD_DIM; i += 256) {
        int r = i >> 6, d = i & 63;
        Ks[r * KPAD + d] = Kb[(size_t)(klo + r) * HEAD_DIM + d];
        Vs[r * KPAD + d] = Vb[(size_t)(klo + r) * HEAD_DIM + d];
    }
    for (int i = tid; i < QTILE * HEAD_DIM; i += 256) {
        int r = i >> 6, d = i & 63;
        Qs[r * KPAD + d] = Qb[(size_t)(q0 + r) * HEAD_DIM + d];
    }
    __syncthreads();

    const int w = tid >> 5, lane = tid & 31;
    float* P = Pr + w * KSPAN;
    const int b = bh / NHEAD, h = bh % NHEAD;

    for (int j = 0; j < 8; j++) {
        const int ql = w * 8 + j;
        const int q = q0 + ql;
        const int lo = max(0, q - 127) - klo;
        const int hi = min(SEQ - 1, q + 128) - klo;

        float4 qv[16];
        const float4* qr4 = (const float4*)&Qs[ql * KPAD];
#pragma unroll
        for (int d = 0; d < 16; d++) qv[d] = qr4[d];

        float m = -INFINITY;
        for (int kk = lo + lane; kk <= hi; kk += 32) {
            const float4* kr4 = (const float4*)&Ks[kk * KPAD];
            float s = 0.f;
#pragma unroll
            for (int d = 0; d < 16; d++) {
                float4 kvv = kr4[d];
                s += qv[d].x * kvv.x + qv[d].y * kvv.y + qv[d].z * kvv.z + qv[d].w * kvv.w;
            }
            s *= 0.125f;
            P[kk] = s;
            m = fmaxf(m, s);
        }
#pragma unroll
        for (int o = 16; o; o >>= 1) m = fmaxf(m, __shfl_xor_sync(0xffffffffu, m, o));

        float sum = 0.f;
        for (int kk = lo + lane; kk <= hi; kk += 32) {
            float e = expf(P[kk] - m);
            P[kk] = e;
            sum += e;
        }
#pragma unroll
        for (int o = 16; o; o >>= 1) sum += __shfl_xor_sync(0xffffffffu, sum, o);
        const float invs = 1.f / sum;
        __syncwarp();

        float2 acc = make_float2(0.f, 0.f);
        for (int kk = lo; kk <= hi; kk++) {
            float p = P[kk];
            float2 vv = *(const float2*)&Vs[kk * KPAD + 2 * lane];
            acc.x += p * vv.x;
            acc.y += p * vv.y;
        }
        size_t ob = ((size_t)(b * SEQ + q)) * D_MODEL + h * HEAD_DIM + 2 * lane;
        __nv_bfloat16 hx, lx, hy, ly;
        split2(acc.x * invs, hx, lx);
        split2(acc.y * invs, hy, ly);
        __nv_bfloat162 hp; hp.x = hx; hp.y = hy;
        __nv_bfloat162 lp; lp.x = lx; lp.y = ly;
        *(__nv_bfloat162*)(OH + ob) = hp;
        *(__nv_bfloat162*)(OL + ob) = lp;
        __syncwarp();
    }
}

// ---------------- residual + (opt bias) + RMSNorm (+opt bf16 split out) ------
__global__ void __launch_bounds__(256)
resid_rmsnorm(const float* __restrict__ A, const float* __restrict__ bias,
              const float* __restrict__ R, const float* __restrict__ g,
              float* __restrict__ out,
              __nv_bfloat16* __restrict__ outH, __nv_bfloat16* __restrict__ outL)
{
    const int row = blockIdx.x;
    const float* a = A + (size_t)row * D_MODEL;
    const float* r = R + (size_t)row * D_MODEL;

    float v[4];
    float ss = 0.f;
#pragma unroll
    for (int i = 0; i < 4; i++) {
        int c = threadIdx.x + i * 256;
        float x = a[c] + ALPHA * r[c];
        if (bias) x += bias[c];
        v[i] = x;
        ss += x * x;
    }
#pragma unroll
    for (int o = 16; o; o >>= 1) ss += __shfl_xor_sync(0xffffffffu, ss, o);

    __shared__ float ws[8];
    if ((threadIdx.x & 31) == 0) ws[threadIdx.x >> 5] = ss;
    __syncthreads();
    if (threadIdx.x < 32) {
        float t = (threadIdx.x < 8) ? ws[threadIdx.x] : 0.f;
#pragma unroll
        for (int o = 4; o; o >>= 1) t += __shfl_xor_sync(0xffffffffu, t, o);
        if (threadIdx.x == 0) ws[0] = t;
    }
    __syncthreads();
    const float rms = rsqrtf(ws[0] * (1.0f / D_MODEL) + EPS);

    float* orow = out + (size_t)row * D_MODEL;
#pragma unroll
    for (int i = 0; i < 4; i++) {
        int c = threadIdx.x + i * 256;
        float y = v[i] * rms * g[c];
        orow[c] = y;
        if (outH) {
            __nv_bfloat16 h, l;
            split2(y, h, l);
            outH[(size_t)row * D_MODEL + c] = h;
            outL[(size_t)row * D_MODEL + c] = l;
        }
    }
}

// ---------------- host orchestration -----------------------------------------
template<int MODE>
static void launch_gemm(const __nv_bfloat16* Ah, const __nv_bfloat16* Al,
                        const __nv_bfloat16* Bh, const __nv_bfloat16* Bl,
                        float* C, __nv_bfloat16* Ho, __nv_bfloat16* Lo,
                        int M, int N, int K)
{
    size_t smem = (size_t)GSTG * STAGE_B;
    cudaFuncSetAttribute(gemm_mma<MODE>, cudaFuncAttributeMaxDynamicSharedMemorySize, (int)smem);
    dim3 grid(N / GBN, M / GBM);
    gemm_mma<MODE><<<grid, 256, smem>>>(Ah, Al, Bh, Bl, C, Ho, Lo, M, N, K);
}

extern "C" void kernel_launch(void* const* d_in, const int* in_sizes, int n_in,
                              void* d_out, int out_size)
{
    const float* x    = (const float*)d_in[0];
    const float* Wqkv = (const float*)d_in[1];
    const float* Wout = (const float*)d_in[2];
    const float* bout = (const float*)d_in[3];
    const float* W1   = (const float*)d_in[4];
    const float* W2   = (const float*)d_in[5];
    const float* g1   = (const float*)d_in[6];
    const float* g2   = (const float*)d_in[7];
    float* out = (float*)d_out;

    float *qkv, *Qp, *Kp, *Vp, *Ap, *x2, *y2;
    cudaGetSymbolAddress((void**)&qkv, g_qkv);
    cudaGetSymbolAddress((void**)&Qp,  g_q);
    cudaGetSymbolAddress((void**)&Kp,  g_k);
    cudaGetSymbolAddress((void**)&Vp,  g_v);
    cudaGetSymbolAddress((void**)&Ap,  g_a);
    cudaGetSymbolAddress((void**)&x2,  g_x2);
    cudaGetSymbolAddress((void**)&y2,  g_y2);

    __nv_bfloat16 *xh,*xl,*oh,*ol,*x2h,*x2l,*hbh,*hbl,*wqh,*wql,*woh,*wol,*w1h,*w1l,*w2h,*w2l;
    cudaGetSymbolAddress((void**)&xh,  g_xh);  cudaGetSymbolAddress((void**)&xl,  g_xl);
    cudaGetSymbolAddress((void**)&oh,  g_oh);  cudaGetSymbolAddress((void**)&ol,  g_ol);
    cudaGetSymbolAddress((void**)&x2h, g_x2h); cudaGetSymbolAddress((void**)&x2l, g_x2l);
    cudaGetSymbolAddress((void**)&hbh, g_hbh); cudaGetSymbolAddress((void**)&hbl, g_hbl);
    cudaGetSymbolAddress((void**)&wqh, g_wqh); cudaGetSymbolAddress((void**)&wql, g_wql);
    cudaGetSymbolAddress((void**)&woh, g_woh); cudaGetSymbolAddress((void**)&wol, g_wol);
    cudaGetSymbolAddress((void**)&w1h, g_w1h); cudaGetSymbolAddress((void**)&w1l, g_w1l);
    cudaGetSymbolAddress((void**)&w2h, g_w2h); cudaGetSymbolAddress((void**)&w2l, g_w2l);

    // ---- operand splits (weights + input) ----
    {
        int n;
        n = MTOT * D_MODEL / 4;           split_bf16   <<<(n+255)/256, 256>>>(x,    xh,  xl,  n);
        n = 3*D_MODEL * D_MODEL / 4;      split_bf16   <<<(n+255)/256, 256>>>(Wqkv, wqh, wql, n);
        n = D_MODEL * D_MODEL / 4;        split_bf16   <<<(n+255)/256, 256>>>(Wout, woh, wol, n);
        n = 2*FF * D_MODEL / 4;           split_bf16_w1<<<(n+255)/256, 256>>>(W1,   w1h, w1l, n);
        n = D_MODEL * FF / 4;             split_bf16   <<<(n+255)/256, 256>>>(W2,   w2h, w2l, n);
    }

    // 1) QKV = X @ Wqkv^T
    launch_gemm<0>(xh, xl, wqh, wql, qkv, nullptr, nullptr, MTOT, 3 * D_MODEL, D_MODEL);

    // 2) RoPE + split heads
    {
        int total = BATCH * SEQ * NHEAD * 32;
        rope_split<<<total / 256, 256>>>(qkv, Qp, Kp, Vp);
    }

    // 3) banded attention -> oh/ol (bf16 hi/lo)
    {
        size_t smem = (size_t)(2 * KSPAN * KPAD + QTILE * KPAD + 8 * KSPAN) * sizeof(float);
        cudaFuncSetAttribute(attn_kernel, cudaFuncAttributeMaxDynamicSharedMemorySize, (int)smem);
        dim3 grid(SEQ / QTILE, BATCH * NHEAD);
        attn_kernel<<<grid, 256, smem>>>(Qp, Kp, Vp, oh, ol);
    }

    // 4) A = O @ Wout^T
    launch_gemm<0>(oh, ol, woh, wol, Ap, nullptr, nullptr, MTOT, D_MODEL, D_MODEL);

    // 5) x2 = rmsnorm(A + bout + ALPHA*x, g1) (+ bf16 split)
    resid_rmsnorm<<<MTOT, 256>>>(Ap, bout, x, g1, x2, x2h, x2l);

    // 6+7) fused: [y|gate] = x2 @ W1perm^T, swiglu -> hb bf16 hi/lo
    launch_gemm<1>(x2h, x2l, w1h, w1l, nullptr, hbh, hbl, MTOT, 2 * FF, D_MODEL);

    // 8) Y2 = H @ W2^T   (K = FF)
    launch_gemm<0>(hbh, hbl, w2h, w2l, y2, nullptr, nullptr, MTOT, D_MODEL, FF);

    // 9) out = rmsnorm(Y2 + ALPHA*x2, g2)
    resid_rmsnorm<<<MTOT, 256>>>(y2, nullptr, x2, g2, out, nullptr, nullptr);
}

// round 5
// speedup vs baseline: 2.4052x; 1.0302x over previous
#include <cuda_runtime.h>
#include <cuda_bf16.h>
#include <math.h>
#include <stdint.h>

// ---------------- problem constants ----------------
#define D_MODEL 1024
#define NHEAD   16
#define HEAD_DIM 64
#define FF      4096
#define ALPHA   1.4142135f
#define EPS     1e-5f
#define BATCH   2
#define SEQ     2048
#define MTOT    (BATCH*SEQ)        // 4096 rows

// ---------------- scratch (device globals; no allocation allowed) ------------
__device__ float g_qkv[(size_t)MTOT * 3 * D_MODEL];
__device__ float g_a  [(size_t)MTOT * D_MODEL];
__device__ float g_x2 [(size_t)MTOT * D_MODEL];
__device__ float g_y2 [(size_t)MTOT * D_MODEL];
__device__ float g_rope[(size_t)SEQ * 64];                // cos[32] | sin[32] per t

// bf16 hi/lo split operands
__device__ __nv_bfloat16 g_xh [(size_t)MTOT * D_MODEL];
__device__ __nv_bfloat16 g_xl [(size_t)MTOT * D_MODEL];
__device__ __nv_bfloat16 g_oh [(size_t)MTOT * D_MODEL];
__device__ __nv_bfloat16 g_ol [(size_t)MTOT * D_MODEL];
__device__ __nv_bfloat16 g_x2h[(size_t)MTOT * D_MODEL];
__device__ __nv_bfloat16 g_x2l[(size_t)MTOT * D_MODEL];
__device__ __nv_bfloat16 g_hbh[(size_t)MTOT * FF];
__device__ __nv_bfloat16 g_hbl[(size_t)MTOT * FF];
__device__ __nv_bfloat16 g_wqh[(size_t)3*D_MODEL * D_MODEL];
__device__ __nv_bfloat16 g_wql[(size_t)3*D_MODEL * D_MODEL];
__device__ __nv_bfloat16 g_woh[(size_t)D_MODEL * D_MODEL];
__device__ __nv_bfloat16 g_wol[(size_t)D_MODEL * D_MODEL];
__device__ __nv_bfloat16 g_w1h[(size_t)2*FF * D_MODEL];   // permuted y/gate interleave
__device__ __nv_bfloat16 g_w1l[(size_t)2*FF * D_MODEL];
__device__ __nv_bfloat16 g_w2h[(size_t)D_MODEL * FF];
__device__ __nv_bfloat16 g_w2l[(size_t)D_MODEL * FF];

// ---------------- PTX helpers -------------------------------------------------
__device__ __forceinline__ uint32_t smem_u32(const void* p) {
    uint32_t a;
    asm("{ .reg .u64 t; cvta.to.shared.u64 t, %1; cvt.u32.u64 %0, t; }" : "=r"(a) : "l"(p));
    return a;
}

#define CP_ASYNC16(dst, src) \
    asm volatile("cp.async.cg.shared.global [%0], [%1], 16;" :: "r"(dst), "l"(src) : "memory")
#define CP_COMMIT() asm volatile("cp.async.commit_group;" ::: "memory")
#define CP_WAIT2()  asm volatile("cp.async.wait_group 2;" ::: "memory")

#define LDSM_X4(r0, r1, r2, r3, addr) \
    asm volatile("ldmatrix.sync.aligned.m8n8.x4.shared.b16 {%0,%1,%2,%3}, [%4];" \
        : "=r"(r0), "=r"(r1), "=r"(r2), "=r"(r3) : "r"(addr))

#define MMA_BF16(d, a, b0v, b1v) \
    asm volatile("mma.sync.aligned.m16n8k16.row.col.f32.bf16.bf16.f32 " \
        "{%0,%1,%2,%3}, {%4,%5,%6,%7}, {%8,%9}, {%0,%1,%2,%3};" \
        : "+f"((d)[0]), "+f"((d)[1]), "+f"((d)[2]), "+f"((d)[3]) \
        : "r"((a)[0]), "r"((a)[1]), "r"((a)[2]), "r"((a)[3]), "r"(b0v), "r"(b1v))

__device__ __forceinline__ void split2(float x, __nv_bfloat16& h, __nv_bfloat16& l) {
    h = __float2bfloat16_rn(x);
    l = __float2bfloat16_rn(x - __bfloat162float(h));
}

// ---------------- HMMA GEMM, term-merged bf16x3 -------------------------------
// C[M,N] = (Ah+Al)[M,K] * ((Bh+Bl)[N,K])^T  via Ah*Bh + Al*Bh + Ah*Bl.
// BM=256, BN=128, BK=32, 4 stages. MMAs issued term-major: 32 independent
// accumulators between dependent reuses -> no HMMA RAW stalls.
// MODE 0: write fp32 C.  MODE 1: cols are (y,gate) pairs -> swiglu -> bf16 h/l.
#define GBM 256
#define GBN 128
#define GK  32
#define GSTG 4
#define TA  (GBM*64)                 // 16 KB
#define TB  (GBN*64)                 // 8 KB
#define STAGE_B (2*TA + 2*TB)        // 48 KB per stage

template<int MODE>
__global__ void __launch_bounds__(256, 1)
gemm_mma(const __nv_bfloat16* __restrict__ Ah, const __nv_bfloat16* __restrict__ Al,
         const __nv_bfloat16* __restrict__ Bh, const __nv_bfloat16* __restrict__ Bl,
         float* __restrict__ C,
         __nv_bfloat16* __restrict__ Ho, __nv_bfloat16* __restrict__ Lo,
         int M, int N, int K)
{
    extern __shared__ __align__(128) char smem[];

    const int tid  = threadIdx.x;
    const int lane = tid & 31;
    const int wid  = tid >> 5;
    const int wm   = wid >> 1;           // 0..3
    const int wn   = wid & 1;            // 0..1
    const int bm   = blockIdx.y * GBM;
    const int bn   = blockIdx.x * GBN;

    const int NK = K / GK;
    const uint32_t sbase = smem_u32(smem);

    const int lrow = tid >> 2;           // 0..63
    const int lcc  = tid & 3;            // 0..3

    auto load_stage = [&](int s, int kc) {
        const uint32_t st = sbase + s * STAGE_B;
#pragma unroll
        for (int half = 0; half < 4; half++) {
            const int row = lrow + half * 64;
            const uint32_t swz = (uint32_t)(row * 64 + ((lcc ^ ((row >> 1) & 3)) << 4));
            CP_ASYNC16(st + swz,       Ah + (size_t)(bm + row) * K + kc * GK + lcc * 8);
            CP_ASYNC16(st + TA + swz,  Al + (size_t)(bm + row) * K + kc * GK + lcc * 8);
        }
#pragma unroll
        for (int half = 0; half < 2; half++) {
            const int row = lrow + half * 64;
            const uint32_t swz = (uint32_t)(row * 64 + ((lcc ^ ((row >> 1) & 3)) << 4));
            CP_ASYNC16(st + 2*TA + swz,      Bh + (size_t)(bn + row) * K + kc * GK + lcc * 8);
            CP_ASYNC16(st + 2*TA + TB + swz, Bl + (size_t)(bn + row) * K + kc * GK + lcc * 8);
        }
    };

    float acc[4][8][4];
#pragma unroll
    for (int mi = 0; mi < 4; mi++)
#pragma unroll
        for (int ni = 0; ni < 8; ni++)
#pragma unroll
            for (int r = 0; r < 4; r++) acc[mi][ni][r] = 0.f;

    load_stage(0, 0); CP_COMMIT();
    if (NK > 1) load_stage(1, 1); CP_COMMIT();
    if (NK > 2) load_stage(2, 2); CP_COMMIT();

    const int m_idx = lane >> 3;

    for (int c = 0; c < NK; c++) {
        CP_WAIT2();
        __syncthreads();
        if (c + 3 < NK) load_stage((c + 3) & 3, c + 3);
        CP_COMMIT();

        const uint32_t st = sbase + (c & 3) * STAGE_B;
        const uint32_t Ahb = st, Alb = st + TA, Bhb = st + 2*TA, Blb = st + 2*TA + TB;

#pragma unroll
        for (int ks = 0; ks < 2; ks++) {
            uint32_t afh[4][4], afl[4][4], bfh[4][4], bfl[4][4];
#pragma unroll
            for (int mi = 0; mi < 4; mi++) {
                const int row = wm * 64 + mi * 16 + (lane & 7) + ((m_idx & 1) << 3);
                const int cch = 2 * ks + (m_idx >> 1);
                const uint32_t off = (uint32_t)(row * 64 + ((cch ^ ((row >> 1) & 3)) << 4));
                LDSM_X4(afh[mi][0], afh[mi][1], afh[mi][2], afh[mi][3], Ahb + off);
                LDSM_X4(afl[mi][0], afl[mi][1], afl[mi][2], afl[mi][3], Alb + off);
            }
#pragma unroll
            for (int pi = 0; pi < 4; pi++) {
                const int nrow = wn * 64 + pi * 16 + (lane & 7) + ((m_idx >> 1) << 3);
                const int cch = 2 * ks + (m_idx & 1);
                const uint32_t off = (uint32_t)(nrow * 64 + ((cch ^ ((nrow >> 1) & 3)) << 4));
                LDSM_X4(bfh[pi][0], bfh[pi][1], bfh[pi][2], bfh[pi][3], Bhb + off);
                LDSM_X4(bfl[pi][0], bfl[pi][1], bfl[pi][2], bfl[pi][3], Blb + off);
            }
            // term 0: Ah x Bh   (32 independent MMAs)
#pragma unroll
            for (int mi = 0; mi < 4; mi++)
#pragma unroll
                for (int ni = 0; ni < 8; ni++)
                    MMA_BF16(acc[mi][ni], afh[mi],
                             bfh[ni >> 1][(ni & 1) * 2], bfh[ni >> 1][(ni & 1) * 2 + 1]);
            // term 1: Al x Bh
#pragma unroll
            for (int mi = 0; mi < 4; mi++)
#pragma unroll
                for (int ni = 0; ni < 8; ni++)
                    MMA_BF16(acc[mi][ni], afl[mi],
                             bfh[ni >> 1][(ni & 1) * 2], bfh[ni >> 1][(ni & 1) * 2 + 1]);
            // term 2: Ah x Bl
#pragma unroll
            for (int mi = 0; mi < 4; mi++)
#pragma unroll
                for (int ni = 0; ni < 8; ni++)
                    MMA_BF16(acc[mi][ni], afh[mi],
                             bfl[ni >> 1][(ni & 1) * 2], bfl[ni >> 1][(ni & 1) * 2 + 1]);
        }
    }

    // epilogue
#pragma unroll
    for (int mi = 0; mi < 4; mi++) {
        const int row0 = bm + wm * 64 + mi * 16 + (lane >> 2);
#pragma unroll
        for (int ni = 0; ni < 8; ni++) {
            const int col = bn + wn * 64 + ni * 8 + (lane & 3) * 2;
            if (MODE == 0) {
                *(float2*)(C + (size_t)row0 * N + col)       = make_float2(acc[mi][ni][0], acc[mi][ni][1]);
                *(float2*)(C + (size_t)(row0 + 8) * N + col) = make_float2(acc[mi][ni][2], acc[mi][ni][3]);
            } else {
                const int Nout = N >> 1;
                const int j = col >> 1;
                float y0 = acc[mi][ni][0], gt0 = acc[mi][ni][1];
                float y1 = acc[mi][ni][2], gt1 = acc[mi][ni][3];
                float h0 = y0 * gt0 / (1.f + expf(-gt0));
                float h1 = y1 * gt1 / (1.f + expf(-gt1));
                __nv_bfloat16 hh, ll;
                split2(h0, hh, ll);
                Ho[(size_t)row0 * Nout + j] = hh;
                Lo[(size_t)row0 * Nout + j] = ll;
                split2(h1, hh, ll);
                Ho[(size_t)(row0 + 8) * Nout + j] = hh;
                Lo[(size_t)(row0 + 8) * Nout + j] = ll;
            }
        }
    }
}

// ---------------- merged operand split + rope table ---------------------------
#define NS_X   (MTOT*D_MODEL/4)
#define NS_WQ  (3*D_MODEL*D_MODEL/4)
#define NS_WO  (D_MODEL*D_MODEL/4)
#define NS_W1  (2*FF*D_MODEL/4)
#define NS_W2  (D_MODEL*FF/4)
#define NS_SPLIT (NS_X + NS_WQ + NS_WO + NS_W1 + NS_W2)
#define NS_ROPE (SEQ*32)
#define NS_TOTAL (NS_SPLIT + NS_ROPE)

__global__ void __launch_bounds__(256)
split_all(const float* __restrict__ x, const float* __restrict__ Wqkv,
          const float* __restrict__ Wout, const float* __restrict__ W1,
          const float* __restrict__ W2,
          __nv_bfloat16* __restrict__ xh,  __nv_bfloat16* __restrict__ xl,
          __nv_bfloat16* __restrict__ wqh, __nv_bfloat16* __restrict__ wql,
          __nv_bfloat16* __restrict__ woh, __nv_bfloat16* __restrict__ wol,
          __nv_bfloat16* __restrict__ w1h, __nv_bfloat16* __restrict__ w1l,
          __nv_bfloat16* __restrict__ w2h, __nv_bfloat16* __restrict__ w2l,
          float* __restrict__ rope)
{
    int i = blockIdx.x * blockDim.x + threadIdx.x;
    if (i >= NS_TOTAL) return;

    if (i >= NS_SPLIT) {
        int j = i - NS_SPLIT;
        int t = j >> 5, dd = j & 31;
        float inv = powf(10000.0f, -(float)dd / 32.0f);
        float s, c;
        sincosf((float)t * inv, &s, &c);
        rope[t * 64 + dd]      = c;
        rope[t * 64 + 32 + dd] = s;
        return;
    }

    const float* src;
    __nv_bfloat16 *H, *L;
    size_t o;
    if (i < NS_X) {
        src = x; H = xh; L = xl; o = i;
    } else if (i < NS_X + NS_WQ) {
        int k = i - NS_X; src = Wqkv; H = wqh; L = wql; o = k;
    } else if (i < NS_X + NS_WQ + NS_WO) {
        int k = i - NS_X - NS_WQ; src = Wout; H = woh; L = wol; o = k;
    } else if (i < NS_X + NS_WQ + NS_WO + NS_W1) {
        int k = i - NS_X - NS_WQ - NS_WO;
        int flat = k * 4;
        int row = flat >> 10;
        int col = flat & (D_MODEL - 1);
        int prow = (row < FF) ? (2 * row) : (2 * (row - FF) + 1);
        src = W1; H = w1h; L = w1l;
        float4 v = ((const float4*)src)[k];
        __nv_bfloat16 h[4], l[4];
        split2(v.x, h[0], l[0]); split2(v.y, h[1], l[1]);
        split2(v.z, h[2], l[2]); split2(v.w, h[3], l[3]);
        o = ((size_t)prow * D_MODEL + col) >> 2;
        ((uint2*)H)[o] = *(uint2*)h;
        ((uint2*)L)[o] = *(uint2*)l;
        return;
    } else {
        int k = i - NS_X - NS_WQ - NS_WO - NS_W1;
        src = W2; H = w2h; L = w2l; o = k;
    }
    float4 v = ((const float4*)src)[o];
    __nv_bfloat16 h[4], l[4];
    split2(v.x, h[0], l[0]); split2(v.y, h[1], l[1]);
    split2(v.z, h[2], l[2]); split2(v.w, h[3], l[3]);
    ((uint2*)H)[o] = *(uint2*)h;
    ((uint2*)L)[o] = *(uint2*)l;
}

// ---------------- banded attention, RoPE fused (reads qkv directly) ----------
#define QTILE 64
#define KSPAN 320
#define KPAD  68

__global__ void __launch_bounds__(256)
attn_kernel(const float* __restrict__ qkv, const float* __restrict__ rope,
            __nv_bfloat16* __restrict__ OH, __nv_bfloat16* __restrict__ OL)
{
    extern __shared__ float sm[];
    float* Ks = sm;
    float* Vs = Ks + KSPAN * KPAD;
    float* Qs = Vs + KSPAN * KPAD;
    float* Pr = Qs + QTILE * KPAD;

    const int bh = blockIdx.y;
    const int b = bh >> 4, h = bh & 15;
    const int q0 = blockIdx.x * QTILE;
    const int klo = max(0, q0 - 127);
    const int khi = min(SEQ - 1, q0 + QTILE - 1 + 128);
    const int nk = khi - klo + 1;

    const int tid = threadIdx.x;

    // K (rope) + V tiles
    for (int i = tid; i < nk * 32; i += 256) {
        int r = i >> 5, dd = i & 31;
        int t = klo + r;
        const float* base = qkv + (size_t)(b * SEQ + t) * (3 * D_MODEL) + h * HEAD_DIM;
        float c0 = rope[t * 64 + dd], s0 = rope[t * 64 + 32 + dd];
        float k1 = base[D_MODEL + dd], k2 = base[D_MODEL + 32 + dd];
        Ks[r * KPAD + dd]      = k1 * c0 - k2 * s0;
        Ks[r * KPAD + 32 + dd] = k2 * c0 + k1 * s0;
        Vs[r * KPAD + dd]      = base[2 * D_MODEL + dd];
        Vs[r * KPAD + 32 + dd] = base[2 * D_MODEL + 32 + dd];
    }
    // Q tile (rope)
    for (int i = tid; i < QTILE * 32; i += 256) {
        int r = i >> 5, dd = i & 31;
        int t = q0 + r;
        const float* base = qkv + (size_t)(b * SEQ + t) * (3 * D_MODEL) + h * HEAD_DIM;
        float c0 = rope[t * 64 + dd], s0 = rope[t * 64 + 32 + dd];
        float q1 = base[dd], q2 = base[32 + dd];
        Qs[r * KPAD + dd]      = q1 * c0 - q2 * s0;
        Qs[r * KPAD + 32 + dd] = q2 * c0 + q1 * s0;
    }
    __syncthreads();

    const int w = tid >> 5, lane = tid & 31;
    float* P = Pr + w * KSPAN;

    for (int j = 0; j < 8; j++) {
        const int ql = w * 8 + j;
        const int q = q0 + ql;
        const int lo = max(0, q - 127) - klo;
        const int hi = min(SEQ - 1, q + 128) - klo;

        float4 qv[16];
        const float4* qr4 = (const float4*)&Qs[ql * KPAD];
#pragma unroll
        for (int d = 0; d < 16; d++) qv[d] = qr4[d];

        float m = -INFINITY;
        for (int kk = lo + lane; kk <= hi; kk += 32) {
            const float4* kr4 = (const float4*)&Ks[kk * KPAD];
            float s = 0.f;
#pragma unroll
            for (int d = 0; d < 16; d++) {
                float4 kvv = kr4[d];
                s += qv[d].x * kvv.x + qv[d].y * kvv.y + qv[d].z * kvv.z + qv[d].w * kvv.w;
            }
            s *= 0.125f;
            P[kk] = s;
            m = fmaxf(m, s);
        }
#pragma unroll
        for (int o = 16; o; o >>= 1) m = fmaxf(m, __shfl_xor_sync(0xffffffffu, m, o));

        float sum = 0.f;
        for (int kk = lo + lane; kk <= hi; kk += 32) {
            float e = expf(P[kk] - m);
            P[kk] = e;
            sum += e;
        }
#pragma unroll
        for (int o = 16; o; o >>= 1) sum += __shfl_xor_sync(0xffffffffu, sum, o);
        const float invs = 1.f / sum;
        __syncwarp();

        float2 acc = make_float2(0.f, 0.f);
        for (int kk = lo; kk <= hi; kk++) {
            float p = P[kk];
            float2 vv = *(const float2*)&Vs[kk * KPAD + 2 * lane];
            acc.x += p * vv.x;
            acc.y += p * vv.y;
        }
        size_t ob = ((size_t)(b * SEQ + q)) * D_MODEL + h * HEAD_DIM + 2 * lane;
        __nv_bfloat16 hx, lx, hy, ly;
        split2(acc.x * invs, hx, lx);
        split2(acc.y * invs, hy, ly);
        __nv_bfloat162 hp; hp.x = hx; hp.y = hy;
        __nv_bfloat162 lp; lp.x = lx; lp.y = ly;
        *(__nv_bfloat162*)(OH + ob) = hp;
        *(__nv_bfloat162*)(OL + ob) = lp;
        __syncwarp();
    }
}

// ---------------- residual + (opt bias) + RMSNorm (+opt bf16 split out) ------
__global__ void __launch_bounds__(256)
resid_rmsnorm(const float* __restrict__ A, const float* __restrict__ bias,
              const float* __restrict__ R, const float* __restrict__ g,
              float* __restrict__ out,
              __nv_bfloat16* __restrict__ outH, __nv_bfloat16* __restrict__ outL)
{
    const int row = blockIdx.x;
    const float* a = A + (size_t)row * D_MODEL;
    const float* r = R + (size_t)row * D_MODEL;

    float v[4];
    float ss = 0.f;
#pragma unroll
    for (int i = 0; i < 4; i++) {
        int c = threadIdx.x + i * 256;
        float x = a[c] + ALPHA * r[c];
        if (bias) x += bias[c];
        v[i] = x;
        ss += x * x;
    }
#pragma unroll
    for (int o = 16; o; o >>= 1) ss += __shfl_xor_sync(0xffffffffu, ss, o);

    __shared__ float ws[8];
    if ((threadIdx.x & 31) == 0) ws[threadIdx.x >> 5] = ss;
    __syncthreads();
    if (threadIdx.x < 32) {
        float t = (threadIdx.x < 8) ? ws[threadIdx.x] : 0.f;
#pragma unroll
        for (int o = 4; o; o >>= 1) t += __shfl_xor_sync(0xffffffffu, t, o);
        if (threadIdx.x == 0) ws[0] = t;
    }
    __syncthreads();
    const float rms = rsqrtf(ws[0] * (1.0f / D_MODEL) + EPS);

    float* orow = out + (size_t)row * D_MODEL;
#pragma unroll
    for (int i = 0; i < 4; i++) {
        int c = threadIdx.x + i * 256;
        float y = v[i] * rms * g[c];
        orow[c] = y;
        if (outH) {
            __nv_bfloat16 h, l;
            split2(y, h, l);
            outH[(size_t)row * D_MODEL + c] = h;
            outL[(size_t)row * D_MODEL + c] = l;
        }
    }
}

// ---------------- host orchestration -----------------------------------------
template<int MODE>
static void launch_gemm(const __nv_bfloat16* Ah, const __nv_bfloat16* Al,
                        const __nv_bfloat16* Bh, const __nv_bfloat16* Bl,
                        float* C, __nv_bfloat16* Ho, __nv_bfloat16* Lo,
                        int M, int N, int K)
{
    size_t smem = (size_t)GSTG * STAGE_B;
    cudaFuncSetAttribute(gemm_mma<MODE>, cudaFuncAttributeMaxDynamicSharedMemorySize, (int)smem);
    dim3 grid(N / GBN, M / GBM);
    gemm_mma<MODE><<<grid, 256, smem>>>(Ah, Al, Bh, Bl, C, Ho, Lo, M, N, K);
}

extern "C" void kernel_launch(void* const* d_in, const int* in_sizes, int n_in,
                              void* d_out, int out_size)
{
    const float* x    = (const float*)d_in[0];
    const float* Wqkv = (const float*)d_in[1];
    const float* Wout = (const float*)d_in[2];
    const float* bout = (const float*)d_in[3];
    const float* W1   = (const float*)d_in[4];
    const float* W2   = (const float*)d_in[5];
    const float* g1   = (const float*)d_in[6];
    const float* g2   = (const float*)d_in[7];
    float* out = (float*)d_out;

    float *qkv, *Ap, *x2, *y2, *rope;
    cudaGetSymbolAddress((void**)&qkv,  g_qkv);
    cudaGetSymbolAddress((void**)&Ap,   g_a);
    cudaGetSymbolAddress((void**)&x2,   g_x2);
    cudaGetSymbolAddress((void**)&y2,   g_y2);
    cudaGetSymbolAddress((void**)&rope, g_rope);

    __nv_bfloat16 *xh,*xl,*oh,*ol,*x2h,*x2l,*hbh,*hbl,*wqh,*wql,*woh,*wol,*w1h,*w1l,*w2h,*w2l;
    cudaGetSymbolAddress((void**)&xh,  g_xh);  cudaGetSymbolAddress((void**)&xl,  g_xl);
    cudaGetSymbolAddress((void**)&oh,  g_oh);  cudaGetSymbolAddress((void**)&ol,  g_ol);
    cudaGetSymbolAddress((void**)&x2h, g_x2h); cudaGetSymbolAddress((void**)&x2l, g_x2l);
    cudaGetSymbolAddress((void**)&hbh, g_hbh); cudaGetSymbolAddress((void**)&hbl, g_hbl);
    cudaGetSymbolAddress((void**)&wqh, g_wqh); cudaGetSymbolAddress((void**)&wql, g_wql);
    cudaGetSymbolAddress((void**)&woh, g_woh); cudaGetSymbolAddress((void**)&wol, g_wol);
    cudaGetSymbolAddress((void**)&w1h, g_w1h); cudaGetSymbolAddress((void**)&w1l, g_w1l);
    cudaGetSymbolAddress((void**)&w2h, g_w2h); cudaGetSymbolAddress((void**)&w2l, g_w2l);

    // 0) merged splits + rope table                                  [launch 0]
    split_all<<<(NS_TOTAL + 255) / 256, 256>>>(x, Wqkv, Wout, W1, W2,
        xh, xl, wqh, wql, woh, wol, w1h, w1l, w2h, w2l, rope);

    // 1) QKV = X @ Wqkv^T                                            [launch 1]
    launch_gemm<0>(xh, xl, wqh, wql, qkv, nullptr, nullptr, MTOT, 3 * D_MODEL, D_MODEL);

    // 2) banded attention (rope fused) -> oh/ol                      [launch 2]
    {
        size_t smem = (size_t)(2 * KSPAN * KPAD + QTILE * KPAD + 8 * KSPAN) * sizeof(float);
        cudaFuncSetAttribute(attn_kernel, cudaFuncAttributeMaxDynamicSharedMemorySize, (int)smem);
        dim3 grid(SEQ / QTILE, BATCH * NHEAD);
        attn_kernel<<<grid, 256, smem>>>(qkv, rope, oh, ol);
    }

    // 3) A = O @ Wout^T                                              [launch 3]
    launch_gemm<0>(oh, ol, woh, wol, Ap, nullptr, nullptr, MTOT, D_MODEL, D_MODEL);

    // 4) x2 = rmsnorm(A + bout + ALPHA*x, g1) (+ bf16 split)         [launch 4]
    resid_rmsnorm<<<MTOT, 256>>>(Ap, bout, x, g1, x2, x2h, x2l);

    // 5) fused: [y|gate] = x2 @ W1perm^T, swiglu -> hb bf16          [launch 5]
    launch_gemm<1>(x2h, x2l, w1h, w1l, nullptr, hbh, hbl, MTOT, 2 * FF, D_MODEL);

    // 6) Y2 = H @ W2^T  (K = FF)                                     [launch 6]
    launch_gemm<0>(hbh, hbl, w2h, w2l, y2, nullptr, nullptr, MTOT, D_MODEL, FF);

    // 7) out = rmsnorm(Y2 + ALPHA*x2, g2)                            [launch 7]
    resid_rmsnorm<<<MTOT, 256>>>(y2, nullptr, x2, g2, out, nullptr, nullptr);
}

// round 6
// speedup vs baseline: 2.7165x; 1.1295x over previous
#include <cuda_runtime.h>
#include <cuda_bf16.h>
#include <math.h>
#include <stdint.h>

// ---------------- problem constants ----------------
#define D_MODEL 1024
#define NHEAD   16
#define HEAD_DIM 64
#define FF      4096
#define ALPHA   1.4142135f
#define EPS     1e-5f
#define BATCH   2
#define SEQ     2048
#define MTOT    (BATCH*SEQ)        // 4096 rows

// ---------------- scratch (device globals; no allocation allowed) ------------
__device__ float g_qkv[(size_t)MTOT * 3 * D_MODEL];
__device__ float g_a  [(size_t)MTOT * D_MODEL];
__device__ float g_x2 [(size_t)MTOT * D_MODEL];
__device__ float g_y2 [(size_t)MTOT * D_MODEL];
__device__ float g_rope[(size_t)SEQ * 64];                // cos[32] | sin[32] per t

// bf16 hi/lo split operands
__device__ __nv_bfloat16 g_xh [(size_t)MTOT * D_MODEL];
__device__ __nv_bfloat16 g_xl [(size_t)MTOT * D_MODEL];
__device__ __nv_bfloat16 g_oh [(size_t)MTOT * D_MODEL];
__device__ __nv_bfloat16 g_ol [(size_t)MTOT * D_MODEL];
__device__ __nv_bfloat16 g_x2h[(size_t)MTOT * D_MODEL];
__device__ __nv_bfloat16 g_x2l[(size_t)MTOT * D_MODEL];
__device__ __nv_bfloat16 g_hbh[(size_t)MTOT * FF];
__device__ __nv_bfloat16 g_hbl[(size_t)MTOT * FF];
__device__ __nv_bfloat16 g_wqh[(size_t)3*D_MODEL * D_MODEL];
__device__ __nv_bfloat16 g_wql[(size_t)3*D_MODEL * D_MODEL];
__device__ __nv_bfloat16 g_woh[(size_t)D_MODEL * D_MODEL];
__device__ __nv_bfloat16 g_wol[(size_t)D_MODEL * D_MODEL];
__device__ __nv_bfloat16 g_w1h[(size_t)2*FF * D_MODEL];   // permuted y/gate interleave
__device__ __nv_bfloat16 g_w1l[(size_t)2*FF * D_MODEL];
__device__ __nv_bfloat16 g_w2h[(size_t)D_MODEL * FF];
__device__ __nv_bfloat16 g_w2l[(size_t)D_MODEL * FF];

// ---------------- PTX helpers -------------------------------------------------
__device__ __forceinline__ uint32_t smem_u32(const void* p) {
    uint32_t a;
    asm("{ .reg .u64 t; cvta.to.shared.u64 t, %1; cvt.u32.u64 %0, t; }" : "=r"(a) : "l"(p));
    return a;
}

#define CP_ASYNC16(dst, src) \
    asm volatile("cp.async.cg.shared.global [%0], [%1], 16;" :: "r"(dst), "l"(src) : "memory")
#define CP_COMMIT() asm volatile("cp.async.commit_group;" ::: "memory")
#define CP_WAIT2()  asm volatile("cp.async.wait_group 2;" ::: "memory")

#define LDSM_X4(r0, r1, r2, r3, addr) \
    asm volatile("ldmatrix.sync.aligned.m8n8.x4.shared.b16 {%0,%1,%2,%3}, [%4];" \
        : "=r"(r0), "=r"(r1), "=r"(r2), "=r"(r3) : "r"(addr))

#define MMA_BF16(d, a, b0v, b1v) \
    asm volatile("mma.sync.aligned.m16n8k16.row.col.f32.bf16.bf16.f32 " \
        "{%0,%1,%2,%3}, {%4,%5,%6,%7}, {%8,%9}, {%0,%1,%2,%3};" \
        : "+f"((d)[0]), "+f"((d)[1]), "+f"((d)[2]), "+f"((d)[3]) \
        : "r"((a)[0]), "r"((a)[1]), "r"((a)[2]), "r"((a)[3]), "r"(b0v), "r"(b1v))

__device__ __forceinline__ void split2(float x, __nv_bfloat16& h, __nv_bfloat16& l) {
    h = __float2bfloat16_rn(x);
    l = __float2bfloat16_rn(x - __bfloat162float(h));
}

// ---------------- HMMA GEMM, term-merged bf16x3 (unchanged from R5) -----------
#define GBM 256
#define GBN 128
#define GK  32
#define GSTG 4
#define TA  (GBM*64)
#define TB  (GBN*64)
#define STAGE_B (2*TA + 2*TB)

template<int MODE>
__global__ void __launch_bounds__(256, 1)
gemm_mma(const __nv_bfloat16* __restrict__ Ah, const __nv_bfloat16* __restrict__ Al,
         const __nv_bfloat16* __restrict__ Bh, const __nv_bfloat16* __restrict__ Bl,
         float* __restrict__ C,
         __nv_bfloat16* __restrict__ Ho, __nv_bfloat16* __restrict__ Lo,
         int M, int N, int K)
{
    extern __shared__ __align__(128) char smem[];

    const int tid  = threadIdx.x;
    const int lane = tid & 31;
    const int wid  = tid >> 5;
    const int wm   = wid >> 1;
    const int wn   = wid & 1;
    const int bm   = blockIdx.y * GBM;
    const int bn   = blockIdx.x * GBN;

    const int NK = K / GK;
    const uint32_t sbase = smem_u32(smem);

    const int lrow = tid >> 2;
    const int lcc  = tid & 3;

    auto load_stage = [&](int s, int kc) {
        const uint32_t st = sbase + s * STAGE_B;
#pragma unroll
        for (int half = 0; half < 4; half++) {
            const int row = lrow + half * 64;
            const uint32_t swz = (uint32_t)(row * 64 + ((lcc ^ ((row >> 1) & 3)) << 4));
            CP_ASYNC16(st + swz,       Ah + (size_t)(bm + row) * K + kc * GK + lcc * 8);
            CP_ASYNC16(st + TA + swz,  Al + (size_t)(bm + row) * K + kc * GK + lcc * 8);
        }
#pragma unroll
        for (int half = 0; half < 2; half++) {
            const int row = lrow + half * 64;
            const uint32_t swz = (uint32_t)(row * 64 + ((lcc ^ ((row >> 1) & 3)) << 4));
            CP_ASYNC16(st + 2*TA + swz,      Bh + (size_t)(bn + row) * K + kc * GK + lcc * 8);
            CP_ASYNC16(st + 2*TA + TB + swz, Bl + (size_t)(bn + row) * K + kc * GK + lcc * 8);
        }
    };

    float acc[4][8][4];
#pragma unroll
    for (int mi = 0; mi < 4; mi++)
#pragma unroll
        for (int ni = 0; ni < 8; ni++)
#pragma unroll
            for (int r = 0; r < 4; r++) acc[mi][ni][r] = 0.f;

    load_stage(0, 0); CP_COMMIT();
    if (NK > 1) load_stage(1, 1); CP_COMMIT();
    if (NK > 2) load_stage(2, 2); CP_COMMIT();

    const int m_idx = lane >> 3;

    for (int c = 0; c < NK; c++) {
        CP_WAIT2();
        __syncthreads();
        if (c + 3 < NK) load_stage((c + 3) & 3, c + 3);
        CP_COMMIT();

        const uint32_t st = sbase + (c & 3) * STAGE_B;
        const uint32_t Ahb = st, Alb = st + TA, Bhb = st + 2*TA, Blb = st + 2*TA + TB;

#pragma unroll
        for (int ks = 0; ks < 2; ks++) {
            uint32_t afh[4][4], afl[4][4], bfh[4][4], bfl[4][4];
#pragma unroll
            for (int mi = 0; mi < 4; mi++) {
                const int row = wm * 64 + mi * 16 + (lane & 7) + ((m_idx & 1) << 3);
                const int cch = 2 * ks + (m_idx >> 1);
                const uint32_t off = (uint32_t)(row * 64 + ((cch ^ ((row >> 1) & 3)) << 4));
                LDSM_X4(afh[mi][0], afh[mi][1], afh[mi][2], afh[mi][3], Ahb + off);
                LDSM_X4(afl[mi][0], afl[mi][1], afl[mi][2], afl[mi][3], Alb + off);
            }
#pragma unroll
            for (int pi = 0; pi < 4; pi++) {
                const int nrow = wn * 64 + pi * 16 + (lane & 7) + ((m_idx >> 1) << 3);
                const int cch = 2 * ks + (m_idx & 1);
                const uint32_t off = (uint32_t)(nrow * 64 + ((cch ^ ((nrow >> 1) & 3)) << 4));
                LDSM_X4(bfh[pi][0], bfh[pi][1], bfh[pi][2], bfh[pi][3], Bhb + off);
                LDSM_X4(bfl[pi][0], bfl[pi][1], bfl[pi][2], bfl[pi][3], Blb + off);
            }
#pragma unroll
            for (int mi = 0; mi < 4; mi++)
#pragma unroll
                for (int ni = 0; ni < 8; ni++)
                    MMA_BF16(acc[mi][ni], afh[mi],
                             bfh[ni >> 1][(ni & 1) * 2], bfh[ni >> 1][(ni & 1) * 2 + 1]);
#pragma unroll
            for (int mi = 0; mi < 4; mi++)
#pragma unroll
                for (int ni = 0; ni < 8; ni++)
                    MMA_BF16(acc[mi][ni], afl[mi],
                             bfh[ni >> 1][(ni & 1) * 2], bfh[ni >> 1][(ni & 1) * 2 + 1]);
#pragma unroll
            for (int mi = 0; mi < 4; mi++)
#pragma unroll
                for (int ni = 0; ni < 8; ni++)
                    MMA_BF16(acc[mi][ni], afh[mi],
                             bfl[ni >> 1][(ni & 1) * 2], bfl[ni >> 1][(ni & 1) * 2 + 1]);
        }
    }

#pragma unroll
    for (int mi = 0; mi < 4; mi++) {
        const int row0 = bm + wm * 64 + mi * 16 + (lane >> 2);
#pragma unroll
        for (int ni = 0; ni < 8; ni++) {
            const int col = bn + wn * 64 + ni * 8 + (lane & 3) * 2;
            if (MODE == 0) {
                *(float2*)(C + (size_t)row0 * N + col)       = make_float2(acc[mi][ni][0], acc[mi][ni][1]);
                *(float2*)(C + (size_t)(row0 + 8) * N + col) = make_float2(acc[mi][ni][2], acc[mi][ni][3]);
            } else {
                const int Nout = N >> 1;
                const int j = col >> 1;
                float y0 = acc[mi][ni][0], gt0 = acc[mi][ni][1];
                float y1 = acc[mi][ni][2], gt1 = acc[mi][ni][3];
                float h0 = y0 * gt0 / (1.f + expf(-gt0));
                float h1 = y1 * gt1 / (1.f + expf(-gt1));
                __nv_bfloat16 hh, ll;
                split2(h0, hh, ll);
                Ho[(size_t)row0 * Nout + j] = hh;
                Lo[(size_t)row0 * Nout + j] = ll;
                split2(h1, hh, ll);
                Ho[(size_t)(row0 + 8) * Nout + j] = hh;
                Lo[(size_t)(row0 + 8) * Nout + j] = ll;
            }
        }
    }
}

// ---------------- merged operand split + rope table ---------------------------
#define NS_X   (MTOT*D_MODEL/4)
#define NS_WQ  (3*D_MODEL*D_MODEL/4)
#define NS_WO  (D_MODEL*D_MODEL/4)
#define NS_W1  (2*FF*D_MODEL/4)
#define NS_W2  (D_MODEL*FF/4)
#define NS_SPLIT (NS_X + NS_WQ + NS_WO + NS_W1 + NS_W2)
#define NS_ROPE (SEQ*32)
#define NS_TOTAL (NS_SPLIT + NS_ROPE)

__global__ void __launch_bounds__(256)
split_all(const float* __restrict__ x, const float* __restrict__ Wqkv,
          const float* __restrict__ Wout, const float* __restrict__ W1,
          const float* __restrict__ W2,
          __nv_bfloat16* __restrict__ xh,  __nv_bfloat16* __restrict__ xl,
          __nv_bfloat16* __restrict__ wqh, __nv_bfloat16* __restrict__ wql,
          __nv_bfloat16* __restrict__ woh, __nv_bfloat16* __restrict__ wol,
          __nv_bfloat16* __restrict__ w1h, __nv_bfloat16* __restrict__ w1l,
          __nv_bfloat16* __restrict__ w2h, __nv_bfloat16* __restrict__ w2l,
          float* __restrict__ rope)
{
    int i = blockIdx.x * blockDim.x + threadIdx.x;
    if (i >= NS_TOTAL) return;

    if (i >= NS_SPLIT) {
        int j = i - NS_SPLIT;
        int t = j >> 5, dd = j & 31;
        float inv = powf(10000.0f, -(float)dd / 32.0f);
        float s, c;
        sincosf((float)t * inv, &s, &c);
        rope[t * 64 + dd]      = c;
        rope[t * 64 + 32 + dd] = s;
        return;
    }

    const float* src;
    __nv_bfloat16 *H, *L;
    size_t o;
    if (i < NS_X) {
        src = x; H = xh; L = xl; o = i;
    } else if (i < NS_X + NS_WQ) {
        int k = i - NS_X; src = Wqkv; H = wqh; L = wql; o = k;
    } else if (i < NS_X + NS_WQ + NS_WO) {
        int k = i - NS_X - NS_WQ; src = Wout; H = woh; L = wol; o = k;
    } else if (i < NS_X + NS_WQ + NS_WO + NS_W1) {
        int k = i - NS_X - NS_WQ - NS_WO;
        int flat = k * 4;
        int row = flat >> 10;
        int col = flat & (D_MODEL - 1);
        int prow = (row < FF) ? (2 * row) : (2 * (row - FF) + 1);
        src = W1; H = w1h; L = w1l;
        float4 v = ((const float4*)src)[k];
        __nv_bfloat16 h[4], l[4];
        split2(v.x, h[0], l[0]); split2(v.y, h[1], l[1]);
        split2(v.z, h[2], l[2]); split2(v.w, h[3], l[3]);
        o = ((size_t)prow * D_MODEL + col) >> 2;
        ((uint2*)H)[o] = *(uint2*)h;
        ((uint2*)L)[o] = *(uint2*)l;
        return;
    } else {
        int k = i - NS_X - NS_WQ - NS_WO - NS_W1;
        src = W2; H = w2h; L = w2l; o = k;
    }
    float4 v = ((const float4*)src)[o];
    __nv_bfloat16 h[4], l[4];
    split2(v.x, h[0], l[0]); split2(v.y, h[1], l[1]);
    split2(v.z, h[2], l[2]); split2(v.w, h[3], l[3]);
    ((uint2*)H)[o] = *(uint2*)h;
    ((uint2*)L)[o] = *(uint2*)l;
}

// ---------------- banded attention v2: key-per-lane outer-product -------------
// Block = (q-tile of 64, b*h). 512 threads, 16 warps x 4 queries.
// Smem: KT (transposed, rope'd K) [64][PADK], V [NKMAX][PADV], Q [64][PADV].
// KT region is reused for normalized P after the score pass.
#define QTILE 64
#define NKMAX 320
#define PADK  321          // odd -> conflict-free transposed writes
#define PADV  66
#define NCH   10           // 320/32 key chunks
#define ATTN_SMEM ((64*PADK + NKMAX*PADV + 64*PADV) * sizeof(float))

__global__ void __launch_bounds__(512)
attn_kernel(const float* __restrict__ qkv, const float* __restrict__ rope,
            __nv_bfloat16* __restrict__ OH, __nv_bfloat16* __restrict__ OL)
{
    extern __shared__ float sm[];
    float* KT = sm;                         // [64][PADK]; later P [64][PADK]
    float* Vs = sm + 64 * PADK;             // [NKMAX][PADV]
    float* Qs = Vs + NKMAX * PADV;          // [64][PADV]

    const int bh = blockIdx.y;
    const int b = bh >> 4, h = bh & 15;
    const int q0 = blockIdx.x * QTILE;
    const int klo = max(0, q0 - 127);
    const int khi = min(SEQ - 1, q0 + QTILE - 1 + 128);
    const int nk = khi - klo + 1;

    const int tid = threadIdx.x;

    // ---- load K (rope'd, transposed) + V ----
    for (int i = tid; i < nk * 32; i += 512) {
        int r = i >> 5, dd = i & 31;
        int t = klo + r;
        const float* base = qkv + (size_t)(b * SEQ + t) * (3 * D_MODEL) + h * HEAD_DIM;
        float c0 = rope[t * 64 + dd], s0 = rope[t * 64 + 32 + dd];
        float k1 = base[D_MODEL + dd], k2 = base[D_MODEL + 32 + dd];
        KT[dd * PADK + r]        = k1 * c0 - k2 * s0;
        KT[(dd + 32) * PADK + r] = k2 * c0 + k1 * s0;
        Vs[r * PADV + dd]        = base[2 * D_MODEL + dd];
        Vs[r * PADV + 32 + dd]   = base[2 * D_MODEL + 32 + dd];
    }
    // ---- load Q (rope'd, row-major) ----
    for (int i = tid; i < QTILE * 32; i += 512) {
        int r = i >> 5, dd = i & 31;
        int t = q0 + r;
        const float* base = qkv + (size_t)(b * SEQ + t) * (3 * D_MODEL) + h * HEAD_DIM;
        float c0 = rope[t * 64 + dd], s0 = rope[t * 64 + 32 + dd];
        float q1 = base[dd], q2 = base[32 + dd];
        Qs[r * PADV + dd]      = q1 * c0 - q2 * s0;
        Qs[r * PADV + 32 + dd] = q2 * c0 + q1 * s0;
    }
    __syncthreads();

    const int w = tid >> 5, lane = tid & 31;
    const int qloc = w * 4;                 // local query base (0..60)
    const int qg0 = q0 + qloc;

    // ---- scores: acc[j][c] = score(query qloc+j, key c*32+lane) ----
    float acc[4][NCH];
#pragma unroll
    for (int j = 0; j < 4; j++)
#pragma unroll
        for (int c = 0; c < NCH; c++) acc[j][c] = 0.f;

#pragma unroll 2
    for (int d = 0; d < HEAD_DIM; d++) {
        float qv0 = Qs[(qloc + 0) * PADV + d];
        float qv1 = Qs[(qloc + 1) * PADV + d];
        float qv2 = Qs[(qloc + 2) * PADV + d];
        float qv3 = Qs[(qloc + 3) * PADV + d];
        const float* kt = KT + d * PADK + lane;
#pragma unroll
        for (int c = 0; c < NCH; c++) {
            float kv = kt[c * 32];
            acc[0][c] += qv0 * kv;
            acc[1][c] += qv1 * kv;
            acc[2][c] += qv2 * kv;
            acc[3][c] += qv3 * kv;
        }
    }

    // ---- mask + softmax (registers, normalized) ----
    float inv[4];
#pragma unroll
    for (int j = 0; j < 4; j++) {
        const int qg = qg0 + j;
        const int lo = max(0, qg - 127) - klo;
        const int hi = min(SEQ - 1, qg + 128) - klo;
        float m = -INFINITY;
#pragma unroll
        for (int c = 0; c < NCH; c++) {
            int kg = c * 32 + lane;
            float s = (kg >= lo && kg <= hi) ? acc[j][c] * 0.125f : -INFINITY;
            acc[j][c] = s;
            m = fmaxf(m, s);
        }
#pragma unroll
        for (int o = 16; o; o >>= 1) m = fmaxf(m, __shfl_xor_sync(0xffffffffu, m, o));
        float sum = 0.f;
#pragma unroll
        for (int c = 0; c < NCH; c++) {
            float e = expf(acc[j][c] - m);
            acc[j][c] = e;
            sum += e;
        }
#pragma unroll
        for (int o = 16; o; o >>= 1) sum += __shfl_xor_sync(0xffffffffu, sum, o);
        inv[j] = 1.f / sum;
    }

    // ---- write normalized P into KT region ----
    __syncthreads();                        // all KT reads complete
    float* P = KT;
#pragma unroll
    for (int j = 0; j < 4; j++)
#pragma unroll
        for (int c = 0; c < NCH; c++)
            P[(qloc + j) * PADK + c * 32 + lane] = acc[j][c] * inv[j];
    __syncthreads();

    // ---- PV: lane owns dims (2*lane, 2*lane+1) ----
    const int kstart = max(0, qg0 - 127) - klo;
    const int kend   = min(SEQ - 1, qg0 + 3 + 128) - klo;

    float ox0 = 0.f, oy0 = 0.f, ox1 = 0.f, oy1 = 0.f;
    float ox2 = 0.f, oy2 = 0.f, ox3 = 0.f, oy3 = 0.f;
    const float* p0 = P + (qloc + 0) * PADK;
    const float* p1 = P + (qloc + 1) * PADK;
    const float* p2 = P + (qloc + 2) * PADK;
    const float* p3 = P + (qloc + 3) * PADK;
    for (int k = kstart; k <= kend; k++) {
        float2 v = *(const float2*)&Vs[k * PADV + 2 * lane];
        float a0 = p0[k], a1 = p1[k], a2 = p2[k], a3 = p3[k];
        ox0 += a0 * v.x; oy0 += a0 * v.y;
        ox1 += a1 * v.x; oy1 += a1 * v.y;
        ox2 += a2 * v.x; oy2 += a2 * v.y;
        ox3 += a3 * v.x; oy3 += a3 * v.y;
    }

    // ---- store bf16 hi/lo ----
    float oxv[4] = {ox0, ox1, ox2, ox3};
    float oyv[4] = {oy0, oy1, oy2, oy3};
#pragma unroll
    for (int j = 0; j < 4; j++) {
        size_t ob = ((size_t)(b * SEQ + qg0 + j)) * D_MODEL + h * HEAD_DIM + 2 * lane;
        __nv_bfloat16 hx, lx, hy, ly;
        split2(oxv[j], hx, lx);
        split2(oyv[j], hy, ly);
        __nv_bfloat162 hp; hp.x = hx; hp.y = hy;
        __nv_bfloat162 lp; lp.x = lx; lp.y = ly;
        *(__nv_bfloat162*)(OH + ob) = hp;
        *(__nv_bfloat162*)(OL + ob) = lp;
    }
}

// ---------------- residual + (opt bias) + RMSNorm (+opt bf16 split out) ------
__global__ void __launch_bounds__(256)
resid_rmsnorm(const float* __restrict__ A, const float* __restrict__ bias,
              const float* __restrict__ R, const float* __restrict__ g,
              float* __restrict__ out,
              __nv_bfloat16* __restrict__ outH, __nv_bfloat16* __restrict__ outL)
{
    const int row = blockIdx.x;
    const float* a = A + (size_t)row * D_MODEL;
    const float* r = R + (size_t)row * D_MODEL;

    float v[4];
    float ss = 0.f;
#pragma unroll
    for (int i = 0; i < 4; i++) {
        int c = threadIdx.x + i * 256;
        float x = a[c] + ALPHA * r[c];
        if (bias) x += bias[c];
        v[i] = x;
        ss += x * x;
    }
#pragma unroll
    for (int o = 16; o; o >>= 1) ss += __shfl_xor_sync(0xffffffffu, ss, o);

    __shared__ float ws[8];
    if ((threadIdx.x & 31) == 0) ws[threadIdx.x >> 5] = ss;
    __syncthreads();
    if (threadIdx.x < 32) {
        float t = (threadIdx.x < 8) ? ws[threadIdx.x] : 0.f;
#pragma unroll
        for (int o = 4; o; o >>= 1) t += __shfl_xor_sync(0xffffffffu, t, o);
        if (threadIdx.x == 0) ws[0] = t;
    }
    __syncthreads();
    const float rms = rsqrtf(ws[0] * (1.0f / D_MODEL) + EPS);

    float* orow = out + (size_t)row * D_MODEL;
#pragma unroll
    for (int i = 0; i < 4; i++) {
        int c = threadIdx.x + i * 256;
        float y = v[i] * rms * g[c];
        orow[c] = y;
        if (outH) {
            __nv_bfloat16 h, l;
            split2(y, h, l);
            outH[(size_t)row * D_MODEL + c] = h;
            outL[(size_t)row * D_MODEL + c] = l;
        }
    }
}

// ---------------- host orchestration -----------------------------------------
template<int MODE>
static void launch_gemm(const __nv_bfloat16* Ah, const __nv_bfloat16* Al,
                        const __nv_bfloat16* Bh, const __nv_bfloat16* Bl,
                        float* C, __nv_bfloat16* Ho, __nv_bfloat16* Lo,
                        int M, int N, int K)
{
    size_t smem = (size_t)GSTG * STAGE_B;
    cudaFuncSetAttribute(gemm_mma<MODE>, cudaFuncAttributeMaxDynamicSharedMemorySize, (int)smem);
    dim3 grid(N / GBN, M / GBM);
    gemm_mma<MODE><<<grid, 256, smem>>>(Ah, Al, Bh, Bl, C, Ho, Lo, M, N, K);
}

extern "C" void kernel_launch(void* const* d_in, const int* in_sizes, int n_in,
                              void* d_out, int out_size)
{
    const float* x    = (const float*)d_in[0];
    const float* Wqkv = (const float*)d_in[1];
    const float* Wout = (const float*)d_in[2];
    const float* bout = (const float*)d_in[3];
    const float* W1   = (const float*)d_in[4];
    const float* W2   = (const float*)d_in[5];
    const float* g1   = (const float*)d_in[6];
    const float* g2   = (const float*)d_in[7];
    float* out = (float*)d_out;

    float *qkv, *Ap, *x2, *y2, *rope;
    cudaGetSymbolAddress((void**)&qkv,  g_qkv);
    cudaGetSymbolAddress((void**)&Ap,   g_a);
    cudaGetSymbolAddress((void**)&x2,   g_x2);
    cudaGetSymbolAddress((void**)&y2,   g_y2);
    cudaGetSymbolAddress((void**)&rope, g_rope);

    __nv_bfloat16 *xh,*xl,*oh,*ol,*x2h,*x2l,*hbh,*hbl,*wqh,*wql,*woh,*wol,*w1h,*w1l,*w2h,*w2l;
    cudaGetSymbolAddress((void**)&xh,  g_xh);  cudaGetSymbolAddress((void**)&xl,  g_xl);
    cudaGetSymbolAddress((void**)&oh,  g_oh);  cudaGetSymbolAddress((void**)&ol,  g_ol);
    cudaGetSymbolAddress((void**)&x2h, g_x2h); cudaGetSymbolAddress((void**)&x2l, g_x2l);
    cudaGetSymbolAddress((void**)&hbh, g_hbh); cudaGetSymbolAddress((void**)&hbl, g_hbl);
    cudaGetSymbolAddress((void**)&wqh, g_wqh); cudaGetSymbolAddress((void**)&wql, g_wql);
    cudaGetSymbolAddress((void**)&woh, g_woh); cudaGetSymbolAddress((void**)&wol, g_wol);
    cudaGetSymbolAddress((void**)&w1h, g_w1h); cudaGetSymbolAddress((void**)&w1l, g_w1l);
    cudaGetSymbolAddress((void**)&w2h, g_w2h); cudaGetSymbolAddress((void**)&w2l, g_w2l);

    // 0) merged splits + rope table
    split_all<<<(NS_TOTAL + 255) / 256, 256>>>(x, Wqkv, Wout, W1, W2,
        xh, xl, wqh, wql, woh, wol, w1h, w1l, w2h, w2l, rope);

    // 1) QKV = X @ Wqkv^T
    launch_gemm<0>(xh, xl, wqh, wql, qkv, nullptr, nullptr, MTOT, 3 * D_MODEL, D_MODEL);

    // 2) banded attention (rope fused) -> oh/ol
    {
        cudaFuncSetAttribute(attn_kernel, cudaFuncAttributeMaxDynamicSharedMemorySize, (int)ATTN_SMEM);
        dim3 grid(SEQ / QTILE, BATCH * NHEAD);
        attn_kernel<<<grid, 512, ATTN_SMEM>>>(qkv, rope, oh, ol);
    }

    // 3) A = O @ Wout^T
    launch_gemm<0>(oh, ol, woh, wol, Ap, nullptr, nullptr, MTOT, D_MODEL, D_MODEL);

    // 4) x2 = rmsnorm(A + bout + ALPHA*x, g1) (+ bf16 split)
    resid_rmsnorm<<<MTOT, 256>>>(Ap, bout, x, g1, x2, x2h, x2l);

    // 5) fused: [y|gate] = x2 @ W1perm^T, swiglu -> hb bf16
    launch_gemm<1>(x2h, x2l, w1h, w1l, nullptr, hbh, hbl, MTOT, 2 * FF, D_MODEL);

    // 6) Y2 = H @ W2^T  (K = FF)
    launch_gemm<0>(hbh, hbl, w2h, w2l, y2, nullptr, nullptr, MTOT, D_MODEL, FF);

    // 7) out = rmsnorm(Y2 + ALPHA*x2, g2)
    resid_rmsnorm<<<MTOT, 256>>>(y2, nullptr, x2, g2, out, nullptr, nullptr);
}

// round 7
// speedup vs baseline: 2.9476x; 1.0851x over previous
#include <cuda_runtime.h>
#include <cuda_bf16.h>
#include <math.h>
#include <stdint.h>

// ---------------- problem constants ----------------
#define D_MODEL 1024
#define NHEAD   16
#define HEAD_DIM 64
#define FF      4096
#define ALPHA   1.4142135f
#define EPS     1e-5f
#define BATCH   2
#define SEQ     2048
#define MTOT    (BATCH*SEQ)        // 4096 rows

// ---------------- scratch (device globals; no allocation allowed) ------------
__device__ float g_qkv[(size_t)MTOT * 3 * D_MODEL];
__device__ float g_a  [(size_t)MTOT * D_MODEL];
__device__ float g_x2 [(size_t)MTOT * D_MODEL];
__device__ float g_y2 [(size_t)MTOT * D_MODEL];
__device__ float g_rope[(size_t)SEQ * 64];                // cos[32] | sin[32] per t

// bf16 hi/lo split operands
__device__ __nv_bfloat16 g_xh [(size_t)MTOT * D_MODEL];
__device__ __nv_bfloat16 g_xl [(size_t)MTOT * D_MODEL];
__device__ __nv_bfloat16 g_oh [(size_t)MTOT * D_MODEL];
__device__ __nv_bfloat16 g_ol [(size_t)MTOT * D_MODEL];
__device__ __nv_bfloat16 g_x2h[(size_t)MTOT * D_MODEL];
__device__ __nv_bfloat16 g_x2l[(size_t)MTOT * D_MODEL];
__device__ __nv_bfloat16 g_hbh[(size_t)MTOT * FF];
__device__ __nv_bfloat16 g_hbl[(size_t)MTOT * FF];
__device__ __nv_bfloat16 g_wqh[(size_t)3*D_MODEL * D_MODEL];
__device__ __nv_bfloat16 g_wql[(size_t)3*D_MODEL * D_MODEL];
__device__ __nv_bfloat16 g_woh[(size_t)D_MODEL * D_MODEL];
__device__ __nv_bfloat16 g_wol[(size_t)D_MODEL * D_MODEL];
__device__ __nv_bfloat16 g_w1h[(size_t)2*FF * D_MODEL];   // permuted y/gate interleave
__device__ __nv_bfloat16 g_w1l[(size_t)2*FF * D_MODEL];
__device__ __nv_bfloat16 g_w2h[(size_t)D_MODEL * FF];
__device__ __nv_bfloat16 g_w2l[(size_t)D_MODEL * FF];

// ---------------- PTX helpers -------------------------------------------------
__device__ __forceinline__ uint32_t smem_u32(const void* p) {
    uint32_t a;
    asm("{ .reg .u64 t; cvta.to.shared.u64 t, %1; cvt.u32.u64 %0, t; }" : "=r"(a) : "l"(p));
    return a;
}

#define CP_ASYNC16(dst, src) \
    asm volatile("cp.async.cg.shared.global [%0], [%1], 16;" :: "r"(dst), "l"(src) : "memory")
#define CP_COMMIT() asm volatile("cp.async.commit_group;" ::: "memory")
#define CP_WAIT1()  asm volatile("cp.async.wait_group 1;" ::: "memory")

#define LDSM_X4(r0, r1, r2, r3, addr) \
    asm volatile("ldmatrix.sync.aligned.m8n8.x4.shared.b16 {%0,%1,%2,%3}, [%4];" \
        : "=r"(r0), "=r"(r1), "=r"(r2), "=r"(r3) : "r"(addr))

#define MMA_BF16(d, a, b0v, b1v) \
    asm volatile("mma.sync.aligned.m16n8k16.row.col.f32.bf16.bf16.f32 " \
        "{%0,%1,%2,%3}, {%4,%5,%6,%7}, {%8,%9}, {%0,%1,%2,%3};" \
        : "+f"((d)[0]), "+f"((d)[1]), "+f"((d)[2]), "+f"((d)[3]) \
        : "r"((a)[0]), "r"((a)[1]), "r"((a)[2]), "r"((a)[3]), "r"(b0v), "r"(b1v))

__device__ __forceinline__ void split2(float x, __nv_bfloat16& h, __nv_bfloat16& l) {
    h = __float2bfloat16_rn(x);
    l = __float2bfloat16_rn(x - __bfloat162float(h));
}

// ---------------- HMMA GEMM, bf16x3, 128x128, 2 CTAs/SM -----------------------
// C[M,N] = (Ah+Al)[M,K] * ((Bh+Bl)[N,K])^T  via Ah*Bh + Al*Bh + Ah*Bl.
// 8 warps in 2x4; warp tile 64x32; GK=32; GSTG=3 (32KB/stage, 96KB/CTA).
// MODE 0: fp32 C.  MODE 1: (y,gate) col pairs -> swiglu -> bf16 h/l.
#define GBM 128
#define GBN 128
#define GK  32
#define GSTG 3
#define TAH (GBM*64)                 // 8 KB: one A tile (hi or lo)
#define TBH (GBN*64)                 // 8 KB
#define STAGE_B (2*TAH + 2*TBH)      // 32 KB per stage

template<int MODE>
__global__ void __launch_bounds__(256, 2)
gemm_mma(const __nv_bfloat16* __restrict__ Ah, const __nv_bfloat16* __restrict__ Al,
         const __nv_bfloat16* __restrict__ Bh, const __nv_bfloat16* __restrict__ Bl,
         float* __restrict__ C,
         __nv_bfloat16* __restrict__ Ho, __nv_bfloat16* __restrict__ Lo,
         int M, int N, int K)
{
    extern __shared__ __align__(128) char smem[];

    const int tid  = threadIdx.x;
    const int lane = tid & 31;
    const int wid  = tid >> 5;
    const int wm   = wid >> 2;           // 0..1
    const int wn   = wid & 3;            // 0..3
    const int bm   = blockIdx.y * GBM;
    const int bn   = blockIdx.x * GBN;

    const int NK = K / GK;
    const uint32_t sbase = smem_u32(smem);

    const int lrow = tid >> 2;           // 0..63
    const int lcc  = tid & 3;            // 0..3

    auto load_stage = [&](int s, int kc) {
        const uint32_t st = sbase + s * STAGE_B;
#pragma unroll
        for (int half = 0; half < 2; half++) {
            const int row = lrow + half * 64;
            const uint32_t swz = (uint32_t)(row * 64 + ((lcc ^ ((row >> 1) & 3)) << 4));
            const size_t ao = (size_t)(bm + row) * K + kc * GK + lcc * 8;
            const size_t bo = (size_t)(bn + row) * K + kc * GK + lcc * 8;
            CP_ASYNC16(st + swz,                Ah + ao);
            CP_ASYNC16(st + TAH + swz,          Al + ao);
            CP_ASYNC16(st + 2*TAH + swz,        Bh + bo);
            CP_ASYNC16(st + 2*TAH + TBH + swz,  Bl + bo);
        }
    };

    float acc[4][4][4];
#pragma unroll
    for (int mi = 0; mi < 4; mi++)
#pragma unroll
        for (int ni = 0; ni < 4; ni++)
#pragma unroll
            for (int r = 0; r < 4; r++) acc[mi][ni][r] = 0.f;

    load_stage(0, 0); CP_COMMIT();
    load_stage(1, 1); CP_COMMIT();

    const int m_idx = lane >> 3;
    int scur = 0, sload = 2;

    for (int c = 0; c < NK; c++) {
        CP_WAIT1();
        __syncthreads();
        if (c + 2 < NK) load_stage(sload, c + 2);
        CP_COMMIT();
        if (++sload == GSTG) sload = 0;

        const uint32_t st = sbase + scur * STAGE_B;
        if (++scur == GSTG) scur = 0;

#pragma unroll
        for (int ks = 0; ks < 2; ks++) {
            uint32_t afh[4][4], afl[4][4], bfh[2][4], bfl[2][4];
#pragma unroll
            for (int mi = 0; mi < 4; mi++) {
                const int row = wm * 64 + mi * 16 + (lane & 7) + ((m_idx & 1) << 3);
                const int cch = 2 * ks + (m_idx >> 1);
                const uint32_t off = (uint32_t)(row * 64 + ((cch ^ ((row >> 1) & 3)) << 4));
                LDSM_X4(afh[mi][0], afh[mi][1], afh[mi][2], afh[mi][3], st + off);
                LDSM_X4(afl[mi][0], afl[mi][1], afl[mi][2], afl[mi][3], st + TAH + off);
            }
#pragma unroll
            for (int pi = 0; pi < 2; pi++) {
                const int nrow = wn * 32 + pi * 16 + (lane & 7) + ((m_idx >> 1) << 3);
                const int cch = 2 * ks + (m_idx & 1);
                const uint32_t off = (uint32_t)(nrow * 64 + ((cch ^ ((nrow >> 1) & 3)) << 4));
                LDSM_X4(bfh[pi][0], bfh[pi][1], bfh[pi][2], bfh[pi][3], st + 2*TAH + off);
                LDSM_X4(bfl[pi][0], bfl[pi][1], bfl[pi][2], bfl[pi][3], st + 2*TAH + TBH + off);
            }
            // term 0: Ah x Bh (16 independent accs)
#pragma unroll
            for (int mi = 0; mi < 4; mi++)
#pragma unroll
                for (int ni = 0; ni < 4; ni++)
                    MMA_BF16(acc[mi][ni], afh[mi],
                             bfh[ni >> 1][(ni & 1) * 2], bfh[ni >> 1][(ni & 1) * 2 + 1]);
            // term 1: Al x Bh
#pragma unroll
            for (int mi = 0; mi < 4; mi++)
#pragma unroll
                for (int ni = 0; ni < 4; ni++)
                    MMA_BF16(acc[mi][ni], afl[mi],
                             bfh[ni >> 1][(ni & 1) * 2], bfh[ni >> 1][(ni & 1) * 2 + 1]);
            // term 2: Ah x Bl
#pragma unroll
            for (int mi = 0; mi < 4; mi++)
#pragma unroll
                for (int ni = 0; ni < 4; ni++)
                    MMA_BF16(acc[mi][ni], afh[mi],
                             bfl[ni >> 1][(ni & 1) * 2], bfl[ni >> 1][(ni & 1) * 2 + 1]);
        }
    }

    // epilogue
#pragma unroll
    for (int mi = 0; mi < 4; mi++) {
        const int row0 = bm + wm * 64 + mi * 16 + (lane >> 2);
#pragma unroll
        for (int ni = 0; ni < 4; ni++) {
            const int col = bn + wn * 32 + ni * 8 + (lane & 3) * 2;
            if (MODE == 0) {
                *(float2*)(C + (size_t)row0 * N + col)       = make_float2(acc[mi][ni][0], acc[mi][ni][1]);
                *(float2*)(C + (size_t)(row0 + 8) * N + col) = make_float2(acc[mi][ni][2], acc[mi][ni][3]);
            } else {
                const int Nout = N >> 1;
                const int j = col >> 1;
                float y0 = acc[mi][ni][0], gt0 = acc[mi][ni][1];
                float y1 = acc[mi][ni][2], gt1 = acc[mi][ni][3];
                float h0 = y0 * gt0 / (1.f + expf(-gt0));
                float h1 = y1 * gt1 / (1.f + expf(-gt1));
                __nv_bfloat16 hh, ll;
                split2(h0, hh, ll);
                Ho[(size_t)row0 * Nout + j] = hh;
                Lo[(size_t)row0 * Nout + j] = ll;
                split2(h1, hh, ll);
                Ho[(size_t)(row0 + 8) * Nout + j] = hh;
                Lo[(size_t)(row0 + 8) * Nout + j] = ll;
            }
        }
    }
}

// ---------------- weight splits -----------------------------------------------
#define NW_WQ  (3*D_MODEL*D_MODEL/4)
#define NW_WO  (D_MODEL*D_MODEL/4)
#define NW_W1  (2*FF*D_MODEL/4)
#define NW_W2  (D_MODEL*FF/4)
#define NW_TOTAL (NW_WQ + NW_WO + NW_W1 + NW_W2)

__global__ void __launch_bounds__(256)
split_w(const float* __restrict__ Wqkv, const float* __restrict__ Wout,
        const float* __restrict__ W1, const float* __restrict__ W2,
        __nv_bfloat16* __restrict__ wqh, __nv_bfloat16* __restrict__ wql,
        __nv_bfloat16* __restrict__ woh, __nv_bfloat16* __restrict__ wol,
        __nv_bfloat16* __restrict__ w1h, __nv_bfloat16* __restrict__ w1l,
        __nv_bfloat16* __restrict__ w2h, __nv_bfloat16* __restrict__ w2l)
{
    int i = blockIdx.x * blockDim.x + threadIdx.x;
    if (i >= NW_TOTAL) return;

    const float* src;
    __nv_bfloat16 *H, *L;
    size_t o;
    if (i < NW_WQ) {
        src = Wqkv; H = wqh; L = wql; o = i;
    } else if (i < NW_WQ + NW_WO) {
        int k = i - NW_WQ; src = Wout; H = woh; L = wol; o = k;
    } else if (i < NW_WQ + NW_WO + NW_W1) {
        int k = i - NW_WQ - NW_WO;
        int flat = k * 4;
        int row = flat >> 10;
        int col = flat & (D_MODEL - 1);
        int prow = (row < FF) ? (2 * row) : (2 * (row - FF) + 1);
        float4 v = ((const float4*)W1)[k];
        __nv_bfloat16 h[4], l[4];
        split2(v.x, h[0], l[0]); split2(v.y, h[1], l[1]);
        split2(v.z, h[2], l[2]); split2(v.w, h[3], l[3]);
        size_t oo = ((size_t)prow * D_MODEL + col) >> 2;
        ((uint2*)w1h)[oo] = *(uint2*)h;
        ((uint2*)w1l)[oo] = *(uint2*)l;
        return;
    } else {
        int k = i - NW_WQ - NW_WO - NW_W1; src = W2; H = w2h; L = w2l; o = k;
    }
    float4 v = ((const float4*)src)[o];
    __nv_bfloat16 h[4], l[4];
    split2(v.x, h[0], l[0]); split2(v.y, h[1], l[1]);
    split2(v.z, h[2], l[2]); split2(v.w, h[3], l[3]);
    ((uint2*)H)[o] = *(uint2*)h;
    ((uint2*)L)[o] = *(uint2*)l;
}

// ---------------- x split + rope table ----------------------------------------
#define NX_X   (MTOT*D_MODEL/4)
#define NX_ROPE (SEQ*32)
#define NX_TOTAL (NX_X + NX_ROPE)

__global__ void __launch_bounds__(256)
split_x_rope(const float* __restrict__ x,
             __nv_bfloat16* __restrict__ xh, __nv_bfloat16* __restrict__ xl,
             float* __restrict__ rope)
{
    int i = blockIdx.x * blockDim.x + threadIdx.x;
    if (i >= NX_TOTAL) return;
    if (i >= NX_X) {
        int j = i - NX_X;
        int t = j >> 5, dd = j & 31;
        float inv = powf(10000.0f, -(float)dd / 32.0f);
        float s, c;
        sincosf((float)t * inv, &s, &c);
        rope[t * 64 + dd]      = c;
        rope[t * 64 + 32 + dd] = s;
        return;
    }
    float4 v = ((const float4*)x)[i];
    __nv_bfloat16 h[4], l[4];
    split2(v.x, h[0], l[0]); split2(v.y, h[1], l[1]);
    split2(v.z, h[2], l[2]); split2(v.w, h[3], l[3]);
    ((uint2*)xh)[i] = *(uint2*)h;
    ((uint2*)xl)[i] = *(uint2*)l;
}

// ---------------- banded attention v2 (unchanged from R6) ---------------------
#define QTILE 64
#define NKMAX 320
#define PADK  321
#define PADV  66
#define NCH   10
#define ATTN_SMEM ((64*PADK + NKMAX*PADV + 64*PADV) * sizeof(float))

__global__ void __launch_bounds__(512)
attn_kernel(const float* __restrict__ qkv, const float* __restrict__ rope,
            __nv_bfloat16* __restrict__ OH, __nv_bfloat16* __restrict__ OL)
{
    extern __shared__ float sm[];
    float* KT = sm;
    float* Vs = sm + 64 * PADK;
    float* Qs = Vs + NKMAX * PADV;

    const int bh = blockIdx.y;
    const int b = bh >> 4, h = bh & 15;
    const int q0 = blockIdx.x * QTILE;
    const int klo = max(0, q0 - 127);
    const int khi = min(SEQ - 1, q0 + QTILE - 1 + 128);
    const int nk = khi - klo + 1;

    const int tid = threadIdx.x;

    for (int i = tid; i < nk * 32; i += 512) {
        int r = i >> 5, dd = i & 31;
        int t = klo + r;
        const float* base = qkv + (size_t)(b * SEQ + t) * (3 * D_MODEL) + h * HEAD_DIM;
        float c0 = rope[t * 64 + dd], s0 = rope[t * 64 + 32 + dd];
        float k1 = base[D_MODEL + dd], k2 = base[D_MODEL + 32 + dd];
        KT[dd * PADK + r]        = k1 * c0 - k2 * s0;
        KT[(dd + 32) * PADK + r] = k2 * c0 + k1 * s0;
        Vs[r * PADV + dd]        = base[2 * D_MODEL + dd];
        Vs[r * PADV + 32 + dd]   = base[2 * D_MODEL + 32 + dd];
    }
    for (int i = tid; i < QTILE * 32; i += 512) {
        int r = i >> 5, dd = i & 31;
        int t = q0 + r;
        const float* base = qkv + (size_t)(b * SEQ + t) * (3 * D_MODEL) + h * HEAD_DIM;
        float c0 = rope[t * 64 + dd], s0 = rope[t * 64 + 32 + dd];
        float q1 = base[dd], q2 = base[32 + dd];
        Qs[r * PADV + dd]      = q1 * c0 - q2 * s0;
        Qs[r * PADV + 32 + dd] = q2 * c0 + q1 * s0;
    }
    __syncthreads();

    const int w = tid >> 5, lane = tid & 31;
    const int qloc = w * 4;
    const int qg0 = q0 + qloc;

    float acc[4][NCH];
#pragma unroll
    for (int j = 0; j < 4; j++)
#pragma unroll
        for (int c = 0; c < NCH; c++) acc[j][c] = 0.f;

#pragma unroll 2
    for (int d = 0; d < HEAD_DIM; d++) {
        float qv0 = Qs[(qloc + 0) * PADV + d];
        float qv1 = Qs[(qloc + 1) * PADV + d];
        float qv2 = Qs[(qloc + 2) * PADV + d];
        float qv3 = Qs[(qloc + 3) * PADV + d];
        const float* kt = KT + d * PADK + lane;
#pragma unroll
        for (int c = 0; c < NCH; c++) {
            float kv = kt[c * 32];
            acc[0][c] += qv0 * kv;
            acc[1][c] += qv1 * kv;
            acc[2][c] += qv2 * kv;
            acc[3][c] += qv3 * kv;
        }
    }

    float inv[4];
#pragma unroll
    for (int j = 0; j < 4; j++) {
        const int qg = qg0 + j;
        const int lo = max(0, qg - 127) - klo;
        const int hi = min(SEQ - 1, qg + 128) - klo;
        float m = -INFINITY;
#pragma unroll
        for (int c = 0; c < NCH; c++) {
            int kg = c * 32 + lane;
            float s = (kg >= lo && kg <= hi) ? acc[j][c] * 0.125f : -INFINITY;
            acc[j][c] = s;
            m = fmaxf(m, s);
        }
#pragma unroll
        for (int o = 16; o; o >>= 1) m = fmaxf(m, __shfl_xor_sync(0xffffffffu, m, o));
        float sum = 0.f;
#pragma unroll
        for (int c = 0; c < NCH; c++) {
            float e = expf(acc[j][c] - m);
            acc[j][c] = e;
            sum += e;
        }
#pragma unroll
        for (int o = 16; o; o >>= 1) sum += __shfl_xor_sync(0xffffffffu, sum, o);
        inv[j] = 1.f / sum;
    }

    __syncthreads();
    float* P = KT;
#pragma unroll
    for (int j = 0; j < 4; j++)
#pragma unroll
        for (int c = 0; c < NCH; c++)
            P[(qloc + j) * PADK + c * 32 + lane] = acc[j][c] * inv[j];
    __syncthreads();

    const int kstart = max(0, qg0 - 127) - klo;
    const int kend   = min(SEQ - 1, qg0 + 3 + 128) - klo;

    float ox0 = 0.f, oy0 = 0.f, ox1 = 0.f, oy1 = 0.f;
    float ox2 = 0.f, oy2 = 0.f, ox3 = 0.f, oy3 = 0.f;
    const float* p0 = P + (qloc + 0) * PADK;
    const float* p1 = P + (qloc + 1) * PADK;
    const float* p2 = P + (qloc + 2) * PADK;
    const float* p3 = P + (qloc + 3) * PADK;
    for (int k = kstart; k <= kend; k++) {
        float2 v = *(const float2*)&Vs[k * PADV + 2 * lane];
        float a0 = p0[k], a1 = p1[k], a2 = p2[k], a3 = p3[k];
        ox0 += a0 * v.x; oy0 += a0 * v.y;
        ox1 += a1 * v.x; oy1 += a1 * v.y;
        ox2 += a2 * v.x; oy2 += a2 * v.y;
        ox3 += a3 * v.x; oy3 += a3 * v.y;
    }

    float oxv[4] = {ox0, ox1, ox2, ox3};
    float oyv[4] = {oy0, oy1, oy2, oy3};
#pragma unroll
    for (int j = 0; j < 4; j++) {
        size_t ob = ((size_t)(b * SEQ + qg0 + j)) * D_MODEL + h * HEAD_DIM + 2 * lane;
        __nv_bfloat16 hx, lx, hy, ly;
        split2(oxv[j], hx, lx);
        split2(oyv[j], hy, ly);
        __nv_bfloat162 hp; hp.x = hx; hp.y = hy;
        __nv_bfloat162 lp; lp.x = lx; lp.y = ly;
        *(__nv_bfloat162*)(OH + ob) = hp;
        *(__nv_bfloat162*)(OL + ob) = lp;
    }
}

// ---------------- residual + (opt bias) + RMSNorm (+opt bf16 split out) ------
__global__ void __launch_bounds__(256)
resid_rmsnorm(const float* __restrict__ A, const float* __restrict__ bias,
              const float* __restrict__ R, const float* __restrict__ g,
              float* __restrict__ out,
              __nv_bfloat16* __restrict__ outH, __nv_bfloat16* __restrict__ outL)
{
    const int row = blockIdx.x;
    const float* a = A + (size_t)row * D_MODEL;
    const float* r = R + (size_t)row * D_MODEL;

    float v[4];
    float ss = 0.f;
#pragma unroll
    for (int i = 0; i < 4; i++) {
        int c = threadIdx.x + i * 256;
        float x = a[c] + ALPHA * r[c];
        if (bias) x += bias[c];
        v[i] = x;
        ss += x * x;
    }
#pragma unroll
    for (int o = 16; o; o >>= 1) ss += __shfl_xor_sync(0xffffffffu, ss, o);

    __shared__ float ws[8];
    if ((threadIdx.x & 31) == 0) ws[threadIdx.x >> 5] = ss;
    __syncthreads();
    if (threadIdx.x < 32) {
        float t = (threadIdx.x < 8) ? ws[threadIdx.x] : 0.f;
#pragma unroll
        for (int o = 4; o; o >>= 1) t += __shfl_xor_sync(0xffffffffu, t, o);
        if (threadIdx.x == 0) ws[0] = t;
    }
    __syncthreads();
    const float rms = rsqrtf(ws[0] * (1.0f / D_MODEL) + EPS);

    float* orow = out + (size_t)row * D_MODEL;
#pragma unroll
    for (int i = 0; i < 4; i++) {
        int c = threadIdx.x + i * 256;
        float y = v[i] * rms * g[c];
        orow[c] = y;
        if (outH) {
            __nv_bfloat16 h, l;
            split2(y, h, l);
            outH[(size_t)row * D_MODEL + c] = h;
            outL[(size_t)row * D_MODEL + c] = l;
        }
    }
}

// ---------------- host orchestration -----------------------------------------
template<int MODE>
static void launch_gemm(const __nv_bfloat16* Ah, const __nv_bfloat16* Al,
                        const __nv_bfloat16* Bh, const __nv_bfloat16* Bl,
                        float* C, __nv_bfloat16* Ho, __nv_bfloat16* Lo,
                        int M, int N, int K)
{
    size_t smem = (size_t)GSTG * STAGE_B;
    cudaFuncSetAttribute(gemm_mma<MODE>, cudaFuncAttributeMaxDynamicSharedMemorySize, (int)smem);
    dim3 grid(N / GBN, M / GBM);
    gemm_mma<MODE><<<grid, 256, smem>>>(Ah, Al, Bh, Bl, C, Ho, Lo, M, N, K);
}

extern "C" void kernel_launch(void* const* d_in, const int* in_sizes, int n_in,
                              void* d_out, int out_size)
{
    const float* x    = (const float*)d_in[0];
    const float* Wqkv = (const float*)d_in[1];
    const float* Wout = (const float*)d_in[2];
    const float* bout = (const float*)d_in[3];
    const float* W1   = (const float*)d_in[4];
    const float* W2   = (const float*)d_in[5];
    const float* g1   = (const float*)d_in[6];
    const float* g2   = (const float*)d_in[7];
    float* out = (float*)d_out;

    float *qkv, *Ap, *x2, *y2, *rope;
    cudaGetSymbolAddress((void**)&qkv,  g_qkv);
    cudaGetSymbolAddress((void**)&Ap,   g_a);
    cudaGetSymbolAddress((void**)&x2,   g_x2);
    cudaGetSymbolAddress((void**)&y2,   g_y2);
    cudaGetSymbolAddress((void**)&rope, g_rope);

    __nv_bfloat16 *xh,*xl,*oh,*ol,*x2h,*x2l,*hbh,*hbl,*wqh,*wql,*woh,*wol,*w1h,*w1l,*w2h,*w2l;
    cudaGetSymbolAddress((void**)&xh,  g_xh);  cudaGetSymbolAddress((void**)&xl,  g_xl);
    cudaGetSymbolAddress((void**)&oh,  g_oh);  cudaGetSymbolAddress((void**)&ol,  g_ol);
    cudaGetSymbolAddress((void**)&x2h, g_x2h); cudaGetSymbolAddress((void**)&x2l, g_x2l);
    cudaGetSymbolAddress((void**)&hbh, g_hbh); cudaGetSymbolAddress((void**)&hbl, g_hbl);
    cudaGetSymbolAddress((void**)&wqh, g_wqh); cudaGetSymbolAddress((void**)&wql, g_wql);
    cudaGetSymbolAddress((void**)&woh, g_woh); cudaGetSymbolAddress((void**)&wol, g_wol);
    cudaGetSymbolAddress((void**)&w1h, g_w1h); cudaGetSymbolAddress((void**)&w1l, g_w1l);
    cudaGetSymbolAddress((void**)&w2h, g_w2h); cudaGetSymbolAddress((void**)&w2l, g_w2l);

    // 0) weight splits                                                 [launch 0]
    split_w<<<(NW_TOTAL + 255) / 256, 256>>>(Wqkv, Wout, W1, W2,
        wqh, wql, woh, wol, w1h, w1l, w2h, w2l);

    // 1) x split + rope table                                          [launch 1]
    split_x_rope<<<(NX_TOTAL + 255) / 256, 256>>>(x, xh, xl, rope);

    // 2) QKV = X @ Wqkv^T                                              [launch 2]
    launch_gemm<0>(xh, xl, wqh, wql, qkv, nullptr, nullptr, MTOT, 3 * D_MODEL, D_MODEL);

    // 3) banded attention (rope fused) -> oh/ol        [launch 3 -> profiled]
    {
        cudaFuncSetAttribute(attn_kernel, cudaFuncAttributeMaxDynamicSharedMemorySize, (int)ATTN_SMEM);
        dim3 grid(SEQ / QTILE, BATCH * NHEAD);
        attn_kernel<<<grid, 512, ATTN_SMEM>>>(qkv, rope, oh, ol);
    }

    // 4) A = O @ Wout^T                                                [launch 4]
    launch_gemm<0>(oh, ol, woh, wol, Ap, nullptr, nullptr, MTOT, D_MODEL, D_MODEL);

    // 5) x2 = rmsnorm(A + bout + ALPHA*x, g1) (+ bf16 split)           [launch 5]
    resid_rmsnorm<<<MTOT, 256>>>(Ap, bout, x, g1, x2, x2h, x2l);

    // 6) fused: [y|gate] = x2 @ W1perm^T, swiglu -> hb bf16            [launch 6]
    launch_gemm<1>(x2h, x2l, w1h, w1l, nullptr, hbh, hbl, MTOT, 2 * FF, D_MODEL);

    // 7) Y2 = H @ W2^T  (K = FF)                                       [launch 7]
    launch_gemm<0>(hbh, hbl, w2h, w2l, y2, nullptr, nullptr, MTOT, D_MODEL, FF);

    // 8) out = rmsnorm(Y2 + ALPHA*x2, g2)                              [launch 8]
    resid_rmsnorm<<<MTOT, 256>>>(y2, nullptr, x2, g2, out, nullptr, nullptr);
}